// round 6
// baseline (speedup 1.0000x reference)
#include <cuda_runtime.h>
#include <cuda_bf16.h>
#include <math.h>
#include <stdint.h>

#define Bn 16
#define Hn 64
#define Wn 64
#define Cn 256
#define Nn 8
#define Dn 32
#define NROW (Bn*Hn*Wn)   // 65536

// ---------------- scratch (device globals; no allocation) ----------------
__device__ float g_q[NROW*Cn];
__device__ float g_k[NROW*Cn];
__device__ float g_v[NROW*Cn];
__device__ float g_lepe[NROW*Cn];
__device__ float g_pre[NROW*Cn];
__device__ float g_vw[Bn*Hn*Nn*64*32];       // [b][h][n][w][d]
__device__ float g_vh2[Bn*Wn*Nn*64*32];      // [b][w][n][h][d]
__device__ float g_da[Bn*Hn*Nn*Wn];          // [b][h][n][w]
__device__ float g_db[Bn*Wn*Nn*Hn];          // [b][w][n][h]
__device__ __nv_bfloat16 g_qkwh[Bn*Hn*Nn*4096];  // P hi  [b][h][n][i][j]
__device__ __nv_bfloat16 g_qkwl[Bn*Hn*Nn*4096];  // P lo

// bf16 hi/lo split buffers for projection GEMMs
__device__ __nv_bfloat16 g_ahi[NROW*Cn];
__device__ __nv_bfloat16 g_alo[NROW*Cn];
__device__ __nv_bfloat16 g_whi[Cn*Cn];
__device__ __nv_bfloat16 g_wlo[Cn*Cn];

// ---------------- helpers ----------------
__device__ __forceinline__ uint32_t smem_u32(const void* p) {
    uint32_t a;
    asm("{ .reg .u64 t; cvta.to.shared.u64 t, %1; cvt.u32.u64 %0, t; }"
        : "=r"(a) : "l"(p));
    return a;
}

__device__ __forceinline__ uint32_t pack_bf2(float a, float b) {
    return (uint32_t)__bfloat16_as_ushort(__float2bfloat16_rn(a))
         | ((uint32_t)__bfloat16_as_ushort(__float2bfloat16_rn(b)) << 16);
}

__device__ __forceinline__ void split1(float v, __nv_bfloat16& h, __nv_bfloat16& l) {
    h = __float2bfloat16_rn(v);
    l = __float2bfloat16_rn(v - __bfloat162float(h));
}

__device__ __forceinline__ void split4(float4 a, uint2& hv, uint2& lv) {
    float h0 = __bfloat162float(__float2bfloat16_rn(a.x));
    float h1 = __bfloat162float(__float2bfloat16_rn(a.y));
    float h2 = __bfloat162float(__float2bfloat16_rn(a.z));
    float h3 = __bfloat162float(__float2bfloat16_rn(a.w));
    hv.x = pack_bf2(a.x, a.y);
    hv.y = pack_bf2(a.z, a.w);
    lv.x = pack_bf2(a.x - h0, a.y - h1);
    lv.y = pack_bf2(a.z - h2, a.w - h3);
}

__device__ __forceinline__ void ldm4(uint32_t addr, uint32_t& r0, uint32_t& r1,
                                     uint32_t& r2, uint32_t& r3) {
    asm volatile("ldmatrix.sync.aligned.m8n8.x4.shared.b16 {%0,%1,%2,%3}, [%4];"
                 : "=r"(r0), "=r"(r1), "=r"(r2), "=r"(r3) : "r"(addr));
}

__device__ __forceinline__ void mma16816(float* d, const uint32_t* a,
                                         uint32_t b0, uint32_t b1) {
    asm volatile("mma.sync.aligned.m16n8k16.row.col.f32.bf16.bf16.f32 "
                 "{%0,%1,%2,%3}, {%4,%5,%6,%7}, {%8,%9}, {%0,%1,%2,%3};"
                 : "+f"(d[0]), "+f"(d[1]), "+f"(d[2]), "+f"(d[3])
                 : "r"(a[0]), "r"(a[1]), "r"(a[2]), "r"(a[3]), "r"(b0), "r"(b1));
}

// ------------- conversion passes: fp32 -> bf16 hi/lo -------------
__global__ __launch_bounds__(256) void convA_kernel(const float* __restrict__ srcExt, int sel)
{
    const float* src = (sel == 0) ? srcExt : g_pre;
    size_t i = ((size_t)blockIdx.x * 256 + threadIdx.x) * 4;
    float4 v = *(const float4*)(src + i);
    uint2 hv, lv; split4(v, hv, lv);
    *(uint2*)(g_ahi + i) = hv;
    *(uint2*)(g_alo + i) = lv;
}

__global__ __launch_bounds__(256) void convW_kernel(const float* __restrict__ src)
{
    size_t i = ((size_t)blockIdx.x * 256 + threadIdx.x) * 4;
    float4 v = *(const float4*)(src + i);
    uint2 hv, lv; split4(v, hv, lv);
    *(uint2*)(g_whi + i) = hv;
    *(uint2*)(g_wlo + i) = lv;
}

// ------------- projection GEMM (mma.sync bf16 hi/lo, rope fused for q/k) -------------
#define GP 40   // smem pitch (bf16 elems)

__global__ __launch_bounds__(256) void gemm_mma_kernel(
    const float* __restrict__ bias, float* __restrict__ dout,
    int dst_sel, float scale,
    const float* __restrict__ sinp, const float* __restrict__ cosp)
{
    float* outp = (dst_sel == 0) ? g_q : (dst_sel == 1) ? g_k
                : (dst_sel == 2) ? g_v : dout;
    const bool do_rope = (dst_sel <= 1);

    __shared__ __align__(16) __nv_bfloat16 sAhi[128 * GP];
    __shared__ __align__(16) __nv_bfloat16 sAlo[128 * GP];
    __shared__ __align__(16) __nv_bfloat16 sBhi[128 * GP];
    __shared__ __align__(16) __nv_bfloat16 sBlo[128 * GP];

    int tid = threadIdx.x;
    int lane = tid & 31, wid = tid >> 5;
    int warp_m = wid >> 2, warp_n = wid & 3;
    int row0 = blockIdx.x * 128;
    int n0 = blockIdx.y * 128;

    int idx0 = tid, idx1 = tid + 256;
    int r0i = idx0 >> 2, q0 = idx0 & 3;
    int r1i = idx1 >> 2, q1 = idx1 & 3;

    float acc[4][4][4];
#pragma unroll
    for (int i = 0; i < 4; i++)
#pragma unroll
        for (int j = 0; j < 4; j++)
#pragma unroll
            for (int e = 0; e < 4; e++) acc[i][j][e] = 0.f;

    uint4 pf[8];
    {
        size_t a0 = (size_t)(row0 + r0i) * 256 + q0 * 8;
        size_t a1 = (size_t)(row0 + r1i) * 256 + q1 * 8;
        size_t b0 = (size_t)(n0 + r0i) * 256 + q0 * 8;
        size_t b1 = (size_t)(n0 + r1i) * 256 + q1 * 8;
        pf[0] = *(const uint4*)(g_ahi + a0); pf[1] = *(const uint4*)(g_ahi + a1);
        pf[2] = *(const uint4*)(g_alo + a0); pf[3] = *(const uint4*)(g_alo + a1);
        pf[4] = *(const uint4*)(g_whi + b0); pf[5] = *(const uint4*)(g_whi + b1);
        pf[6] = *(const uint4*)(g_wlo + b0); pf[7] = *(const uint4*)(g_wlo + b1);
    }

    uint32_t sAhi_b = smem_u32(sAhi), sAlo_b = smem_u32(sAlo);
    uint32_t sBhi_b = smem_u32(sBhi), sBlo_b = smem_u32(sBlo);

    uint32_t a_off[4], b_off[2];
#pragma unroll
    for (int mi = 0; mi < 4; mi++) {
        int row = warp_m * 64 + mi * 16 + (lane & 15);
        int col = ((lane >> 4) & 1) << 3;
        a_off[mi] = (uint32_t)(row * GP + col) * 2;
    }
#pragma unroll
    for (int p = 0; p < 2; p++) {
        int m = lane >> 3;
        int nrow = warp_n * 32 + p * 16 + ((m >> 1) << 3) + (lane & 7);
        int col = (m & 1) << 3;
        b_off[p] = (uint32_t)(nrow * GP + col) * 2;
    }
    uint32_t st0 = (uint32_t)(r0i * GP + q0 * 8) * 2;
    uint32_t st1 = (uint32_t)(r1i * GP + q1 * 8) * 2;

    for (int kc = 0; kc < 8; kc++) {
        *(uint4*)((char*)sAhi + st0) = pf[0]; *(uint4*)((char*)sAhi + st1) = pf[1];
        *(uint4*)((char*)sAlo + st0) = pf[2]; *(uint4*)((char*)sAlo + st1) = pf[3];
        *(uint4*)((char*)sBhi + st0) = pf[4]; *(uint4*)((char*)sBhi + st1) = pf[5];
        *(uint4*)((char*)sBlo + st0) = pf[6]; *(uint4*)((char*)sBlo + st1) = pf[7];
        __syncthreads();

        if (kc < 7) {
            int kn = (kc + 1) * 32;
            size_t a0 = (size_t)(row0 + r0i) * 256 + kn + q0 * 8;
            size_t a1 = (size_t)(row0 + r1i) * 256 + kn + q1 * 8;
            size_t b0 = (size_t)(n0 + r0i) * 256 + kn + q0 * 8;
            size_t b1 = (size_t)(n0 + r1i) * 256 + kn + q1 * 8;
            pf[0] = *(const uint4*)(g_ahi + a0); pf[1] = *(const uint4*)(g_ahi + a1);
            pf[2] = *(const uint4*)(g_alo + a0); pf[3] = *(const uint4*)(g_alo + a1);
            pf[4] = *(const uint4*)(g_whi + b0); pf[5] = *(const uint4*)(g_whi + b1);
            pf[6] = *(const uint4*)(g_wlo + b0); pf[7] = *(const uint4*)(g_wlo + b1);
        }

#pragma unroll
        for (int ks = 0; ks < 2; ks++) {
            uint32_t kb = (uint32_t)(ks * 16) * 2;
            uint32_t ah[4][4], al[4][4], bh[2][4], bl[2][4];
#pragma unroll
            for (int mi = 0; mi < 4; mi++) {
                ldm4(sAhi_b + a_off[mi] + kb, ah[mi][0], ah[mi][1], ah[mi][2], ah[mi][3]);
                ldm4(sAlo_b + a_off[mi] + kb, al[mi][0], al[mi][1], al[mi][2], al[mi][3]);
            }
#pragma unroll
            for (int p = 0; p < 2; p++) {
                ldm4(sBhi_b + b_off[p] + kb, bh[p][0], bh[p][1], bh[p][2], bh[p][3]);
                ldm4(sBlo_b + b_off[p] + kb, bl[p][0], bl[p][1], bl[p][2], bl[p][3]);
            }
#pragma unroll
            for (int mi = 0; mi < 4; mi++) {
#pragma unroll
                for (int nj = 0; nj < 4; nj++) {
                    int p = nj >> 1, h = (nj & 1) << 1;
                    mma16816(acc[mi][nj], ah[mi], bh[p][h], bh[p][h + 1]);
                    mma16816(acc[mi][nj], ah[mi], bl[p][h], bl[p][h + 1]);
                    mma16816(acc[mi][nj], al[mi], bh[p][h], bh[p][h + 1]);
                }
            }
        }
        __syncthreads();
    }

    // epilogue: bias + scale (+ rope for q/k), fp32 store
#pragma unroll
    for (int mi = 0; mi < 4; mi++) {
        int rbase = row0 + warp_m * 64 + mi * 16 + (lane >> 2);
        int hw0 = rbase & 4095;          // h*64 + w
        int hw8 = (rbase + 8) & 4095;
#pragma unroll
        for (int nj = 0; nj < 4; nj++) {
            int c = n0 + warp_n * 32 + nj * 8 + ((lane & 3) << 1);
            float b0 = __ldg(bias + c), b1 = __ldg(bias + c + 1);
            float2 o0, o1;
            o0.x = (acc[mi][nj][0] + b0) * scale;
            o0.y = (acc[mi][nj][1] + b1) * scale;
            o1.x = (acc[mi][nj][2] + b0) * scale;
            o1.y = (acc[mi][nj][3] + b1) * scale;
            if (do_rope) {
                int d0 = c & 31;
                float s0 = __ldg(sinp + hw0 * 32 + d0);
                float s1 = __ldg(sinp + hw0 * 32 + d0 + 1);
                float c0v = __ldg(cosp + hw0 * 32 + d0);
                float c1v = __ldg(cosp + hw0 * 32 + d0 + 1);
                float xe = o0.x, xo = o0.y;
                o0.x = xe * c0v - xo * s0;
                o0.y = xo * c1v + xe * s1;
                float s0b = __ldg(sinp + hw8 * 32 + d0);
                float s1b = __ldg(sinp + hw8 * 32 + d0 + 1);
                float c0b = __ldg(cosp + hw8 * 32 + d0);
                float c1b = __ldg(cosp + hw8 * 32 + d0 + 1);
                float xe1 = o1.x, xo1 = o1.y;
                o1.x = xe1 * c0b - xo1 * s0b;
                o1.y = xo1 * c1b + xe1 * s1b;
            }
            *(float2*)(outp + (size_t)rbase * 256 + c) = o0;
            *(float2*)(outp + (size_t)(rbase + 8) * 256 + c) = o1;
        }
    }
}

// ---------------- dt -> da/db (rope now fused into GEMM) ----------------
__device__ __forceinline__ float softplusf(float a) {
    return (a > 20.f) ? a : log1pf(expf(a));
}

__global__ __launch_bounds__(256) void dt_kernel(
    const float* __restrict__ x, const float* __restrict__ dtw,
    const float* __restrict__ dtb, const float* __restrict__ Alog)
{
    int r = blockIdx.x;          // (b*64 + h)*64 + w
    int w = r & 63;
    int h = (r >> 6) & 63;
    int b = r >> 12;
    int c = threadIdx.x;
    int n = c >> 5, d = c & 31;

    float xv = x[r * 256 + c];
    float t0 = xv * dtw[d];
    float t1 = xv * dtw[32 + d];
#pragma unroll
    for (int off = 16; off; off >>= 1) {
        t0 += __shfl_down_sync(0xffffffffu, t0, off);
        t1 += __shfl_down_sync(0xffffffffu, t1, off);
    }
    if (d == 0) {
        float bias = dtb[n];
        float Aa = -expf(Alog[n]);
        float da = softplusf(t0 + bias) * Aa;
        float db = softplusf(t1 + bias) * Aa;
        g_da[((b * 64 + h) * 8 + n) * 64 + w] = da;
        g_db[((b * 64 + w) * 8 + n) * 64 + h] = db;
    }
}

// ---------------- LePE depthwise 5x5 conv ----------------
__global__ __launch_bounds__(256) void lepe_kernel(
    const float* __restrict__ lw, const float* __restrict__ lb)
{
    int r = blockIdx.x;
    int w = r & 63, h = (r >> 6) & 63, b = r >> 12;
    int c = threadIdx.x;
    float acc = lb[c];
#pragma unroll
    for (int ki = 0; ki < 5; ki++) {
        int hh = h + ki - 2;
        if ((unsigned)hh >= 64u) continue;
#pragma unroll
        for (int kj = 0; kj < 5; kj++) {
            int ww = w + kj - 2;
            if ((unsigned)ww >= 64u) continue;
            acc += __ldg(&g_v[((b * 64 + hh) * 64 + ww) * 256 + c]) * lw[(ki * 5 + kj) * 256 + c];
        }
    }
    g_lepe[r * 256 + c] = acc;
}

// ---------------- attention (mma.sync bf16 hi/lo) ----------------
// dynamic smem layout (bytes):
#define AT_QHI 0
#define AT_QLO 5120
#define AT_KHI 10240
#define AT_KLO 15360
#define AT_PHI 0          // overlays q/k region after S phase
#define AT_PLO 9216
#define AT_VTHI 20480
#define AT_VTLO 25088
#define AT_WTHI 29696
#define AT_WTLO 34304
#define AT_S    38912     // fp32 [64][66]
#define AT_CS   55808     // fp32 [64]
#define ATTN_SMEM 56064

// S = QK^T (+mask) into fp32 smem. 8 warps: wm=wid>>2 (32 rows), wn=wid&3 (16 cols).
__device__ __forceinline__ void s_phase(uint32_t sbase, int lane, int wid, float* S, const float* cs)
{
    int wm = wid >> 2, wn = wid & 3;
    uint32_t a_off[2];
#pragma unroll
    for (int mi = 0; mi < 2; mi++) {
        int row = wm * 32 + mi * 16 + (lane & 15);
        int col = ((lane >> 4) & 1) << 3;
        a_off[mi] = (uint32_t)(row * GP + col) * 2;
    }
    int m = lane >> 3;
    uint32_t b_off = (uint32_t)((wn * 16 + ((m >> 1) << 3) + (lane & 7)) * GP + ((m & 1) << 3)) * 2;

    float sacc[2][2][4];
#pragma unroll
    for (int a = 0; a < 2; a++)
#pragma unroll
        for (int b2 = 0; b2 < 2; b2++)
#pragma unroll
            for (int e = 0; e < 4; e++) sacc[a][b2][e] = 0.f;

#pragma unroll
    for (int ks = 0; ks < 2; ks++) {
        uint32_t kb = (uint32_t)(ks * 16) * 2;
        uint32_t ah[2][4], al[2][4], bh[4], bl[4];
#pragma unroll
        for (int mi = 0; mi < 2; mi++) {
            ldm4(sbase + AT_QHI + a_off[mi] + kb, ah[mi][0], ah[mi][1], ah[mi][2], ah[mi][3]);
            ldm4(sbase + AT_QLO + a_off[mi] + kb, al[mi][0], al[mi][1], al[mi][2], al[mi][3]);
        }
        ldm4(sbase + AT_KHI + b_off + kb, bh[0], bh[1], bh[2], bh[3]);
        ldm4(sbase + AT_KLO + b_off + kb, bl[0], bl[1], bl[2], bl[3]);
#pragma unroll
        for (int mi = 0; mi < 2; mi++) {
#pragma unroll
            for (int nj = 0; nj < 2; nj++) {
                int h2 = nj * 2;
                mma16816(sacc[mi][nj], ah[mi], bh[h2], bh[h2 + 1]);
                mma16816(sacc[mi][nj], ah[mi], bl[h2], bl[h2 + 1]);
                mma16816(sacc[mi][nj], al[mi], bh[h2], bh[h2 + 1]);
            }
        }
    }
    // write S + segsum mask
#pragma unroll
    for (int mi = 0; mi < 2; mi++) {
#pragma unroll
        for (int nj = 0; nj < 2; nj++) {
            int r0 = wm * 32 + mi * 16 + (lane >> 2);
            int c0 = wn * 16 + nj * 8 + ((lane & 3) << 1);
            float cr0 = cs[r0], cr8 = cs[r0 + 8];
            float cc0 = cs[c0], cc1 = cs[c0 + 1];
            S[r0 * 66 + c0]       = sacc[mi][nj][0] + ((r0 >= c0)     ? cr0 - cc0 : cc0 - cr0);
            S[r0 * 66 + c0 + 1]   = sacc[mi][nj][1] + ((r0 >= c0 + 1) ? cr0 - cc1 : cc1 - cr0);
            S[(r0 + 8) * 66 + c0]     = sacc[mi][nj][2] + ((r0 + 8 >= c0)     ? cr8 - cc0 : cc0 - cr8);
            S[(r0 + 8) * 66 + c0 + 1] = sacc[mi][nj][3] + ((r0 + 8 >= c0 + 1) ? cr8 - cc1 : cc1 - cr8);
        }
    }
}

// PV: acc(16x16 per warp) = P(64x64) @ B^T-stored(32x64). wm=wid>>1, wn=wid&1.
__device__ __forceinline__ void pv_phase(uint32_t sbase, int lane, int wid,
                                         uint32_t bbase_hi, uint32_t bbase_lo, float facc[2][4])
{
    int wm = wid >> 1, wn = wid & 1;
    uint32_t a_off = (uint32_t)((wm * 16 + (lane & 15)) * 72 + (((lane >> 4) & 1) << 3)) * 2;
    int m = lane >> 3;
    uint32_t b_off = (uint32_t)((wn * 16 + ((m >> 1) << 3) + (lane & 7)) * 72 + ((m & 1) << 3)) * 2;
#pragma unroll
    for (int ks = 0; ks < 4; ks++) {
        uint32_t kb = (uint32_t)(ks * 16) * 2;
        uint32_t ah[4], al[4], bh[4], bl[4];
        ldm4(sbase + AT_PHI + a_off + kb, ah[0], ah[1], ah[2], ah[3]);
        ldm4(sbase + AT_PLO + a_off + kb, al[0], al[1], al[2], al[3]);
        ldm4(bbase_hi + b_off + kb, bh[0], bh[1], bh[2], bh[3]);
        ldm4(bbase_lo + b_off + kb, bl[0], bl[1], bl[2], bl[3]);
#pragma unroll
        for (int nj = 0; nj < 2; nj++) {
            int h2 = nj * 2;
            mma16816(facc[nj], ah, bh[h2], bh[h2 + 1]);
            mma16816(facc[nj], ah, bl[h2], bl[h2 + 1]);
            mma16816(facc[nj], al, bh[h2], bh[h2 + 1]);
        }
    }
}

// softmax on fp32 S rows -> bf16 hi/lo P in smem; optionally store P to gmem
__device__ __forceinline__ void softmax_phase(char* sm, int lane, int wid, float* S,
                                              __nv_bfloat16* gh, __nv_bfloat16* gl)
{
#pragma unroll
    for (int rr = 0; rr < 8; rr++) {
        int i = wid * 8 + rr;
        float v0 = S[i * 66 + lane], v1 = S[i * 66 + lane + 32];
        float mx = fmaxf(v0, v1);
#pragma unroll
        for (int off = 16; off; off >>= 1) mx = fmaxf(mx, __shfl_xor_sync(0xffffffffu, mx, off));
        float e0 = expf(v0 - mx), e1 = expf(v1 - mx);
        float s = e0 + e1;
#pragma unroll
        for (int off = 16; off; off >>= 1) s += __shfl_xor_sync(0xffffffffu, s, off);
        float inv = 1.f / s;
        float p0 = e0 * inv, p1 = e1 * inv;
        __nv_bfloat16 h0, l0, h1, l1;
        split1(p0, h0, l0);
        split1(p1, h1, l1);
        *(__nv_bfloat16*)(sm + AT_PHI + (i * 72 + lane) * 2) = h0;
        *(__nv_bfloat16*)(sm + AT_PHI + (i * 72 + lane + 32) * 2) = h1;
        *(__nv_bfloat16*)(sm + AT_PLO + (i * 72 + lane) * 2) = l0;
        *(__nv_bfloat16*)(sm + AT_PLO + (i * 72 + lane + 32) * 2) = l1;
        if (gh) {
            gh[i * 64 + lane] = h0; gh[i * 64 + lane + 32] = h1;
            gl[i * 64 + lane] = l0; gl[i * 64 + lane + 32] = l1;
        }
    }
}

__global__ __launch_bounds__(256) void attn_w_kernel(void)
{
    extern __shared__ char sm[];
    int blk = blockIdx.x;                 // (b*64 + h)*8 + n
    int n = blk & 7;
    int h = (blk >> 3) & 63;
    int b = blk >> 9;
    int tid = threadIdx.x, lane = tid & 31, wid = tid >> 5;
    int qbase = ((b * 64 + h) * 64) * 256 + n * 32;
    float* S = (float*)(sm + AT_S);
    float* cs = (float*)(sm + AT_CS);
    uint32_t sbase = smem_u32(sm);

    for (int e = tid; e < 2048; e += 256) {
        int i = e >> 5, d = e & 31;
        float qv = g_q[qbase + i * 256 + d];
        float kv = g_k[qbase + i * 256 + d];
        float vv = g_v[qbase + i * 256 + d];
        __nv_bfloat16 hh, ll;
        split1(qv, hh, ll);
        *(__nv_bfloat16*)(sm + AT_QHI + (i * GP + d) * 2) = hh;
        *(__nv_bfloat16*)(sm + AT_QLO + (i * GP + d) * 2) = ll;
        split1(kv, hh, ll);
        *(__nv_bfloat16*)(sm + AT_KHI + (i * GP + d) * 2) = hh;
        *(__nv_bfloat16*)(sm + AT_KLO + (i * GP + d) * 2) = ll;
        split1(vv, hh, ll);
        *(__nv_bfloat16*)(sm + AT_VTHI + (d * 72 + i) * 2) = hh;
        *(__nv_bfloat16*)(sm + AT_VTLO + (d * 72 + i) * 2) = ll;
    }
    if (tid == 0) {
        float run = 0.f;
        const float* dap = g_da + blk * 64;
        for (int j = 0; j < 64; j++) { run += dap[j]; cs[j] = run; }
    }
    __syncthreads();

    s_phase(sbase, lane, wid, S, cs);
    __syncthreads();

    softmax_phase(sm, lane, wid, S, g_qkwh + (size_t)blk * 4096, g_qkwl + (size_t)blk * 4096);
    __syncthreads();

    float facc[2][4];
#pragma unroll
    for (int nj = 0; nj < 2; nj++)
#pragma unroll
        for (int e = 0; e < 4; e++) facc[nj][e] = 0.f;
    pv_phase(sbase, lane, wid, sbase + AT_VTHI, sbase + AT_VTLO, facc);

    float* vwp = g_vw + (size_t)blk * 2048;
    int wm = wid >> 1, wn = wid & 1;
#pragma unroll
    for (int nj = 0; nj < 2; nj++) {
        int r0 = wm * 16 + (lane >> 2);
        int d0 = wn * 16 + nj * 8 + ((lane & 3) << 1);
        float2 o0 = {facc[nj][0], facc[nj][1]};
        float2 o1 = {facc[nj][2], facc[nj][3]};
        *(float2*)(vwp + r0 * 32 + d0) = o0;
        *(float2*)(vwp + (r0 + 8) * 32 + d0) = o1;
    }
}

__global__ __launch_bounds__(256) void attn_h_kernel(void)
{
    extern __shared__ char sm[];
    int blk = blockIdx.x;                 // (b*64 + x)*8 + n
    int n = blk & 7;
    int x = (blk >> 3) & 63;
    int b = blk >> 9;
    int tid = threadIdx.x, lane = tid & 31, wid = tid >> 5;
    int qbase = (b * 64 * 64 + x) * 256 + n * 32;
    float* S = (float*)(sm + AT_S);
    float* cs = (float*)(sm + AT_CS);
    uint32_t sbase = smem_u32(sm);

    for (int e = tid; e < 2048; e += 256) {
        int i = e >> 5, d = e & 31;
        float qv = g_q[qbase + i * 16384 + d];
        float kv = g_k[qbase + i * 16384 + d];
        float vv = g_v[qbase + i * 16384 + d];
        float wv = g_vw[((size_t)((b * 64 + i) * 8 + n)) * 2048 + x * 32 + d];
        __nv_bfloat16 hh, ll;
        split1(qv, hh, ll);
        *(__nv_bfloat16*)(sm + AT_QHI + (i * GP + d) * 2) = hh;
        *(__nv_bfloat16*)(sm + AT_QLO + (i * GP + d) * 2) = ll;
        split1(kv, hh, ll);
        *(__nv_bfloat16*)(sm + AT_KHI + (i * GP + d) * 2) = hh;
        *(__nv_bfloat16*)(sm + AT_KLO + (i * GP + d) * 2) = ll;
        split1(vv, hh, ll);
        *(__nv_bfloat16*)(sm + AT_VTHI + (d * 72 + i) * 2) = hh;
        *(__nv_bfloat16*)(sm + AT_VTLO + (d * 72 + i) * 2) = ll;
        split1(wv, hh, ll);
        *(__nv_bfloat16*)(sm + AT_WTHI + (d * 72 + i) * 2) = hh;
        *(__nv_bfloat16*)(sm + AT_WTLO + (d * 72 + i) * 2) = ll;
    }
    if (tid == 0) {
        float run = 0.f;
        const float* dbp = g_db + blk * 64;
        for (int j = 0; j < 64; j++) { run += dbp[j]; cs[j] = run; }
    }
    __syncthreads();

    s_phase(sbase, lane, wid, S, cs);
    __syncthreads();

    softmax_phase(sm, lane, wid, S, nullptr, nullptr);
    __syncthreads();

    float facc1[2][4], facc2[2][4];
#pragma unroll
    for (int nj = 0; nj < 2; nj++)
#pragma unroll
        for (int e = 0; e < 4; e++) { facc1[nj][e] = 0.f; facc2[nj][e] = 0.f; }
    pv_phase(sbase, lane, wid, sbase + AT_VTHI, sbase + AT_VTLO, facc1);
    pv_phase(sbase, lane, wid, sbase + AT_WTHI, sbase + AT_WTLO, facc2);

    float* v2p = g_vh2 + (size_t)blk * 2048;
    int wm = wid >> 1, wn = wid & 1;
#pragma unroll
    for (int nj = 0; nj < 2; nj++) {
        int r0 = wm * 16 + (lane >> 2);
        int d0 = wn * 16 + nj * 8 + ((lane & 3) << 1);
        float2 o0 = {facc1[nj][0], facc1[nj][1]};
        float2 o1 = {facc1[nj][2], facc1[nj][3]};
        *(float2*)(v2p + r0 * 32 + d0) = o0;
        *(float2*)(v2p + (r0 + 8) * 32 + d0) = o1;
        float2 p0 = {0.5f * facc2[nj][0], 0.5f * facc2[nj][1]};
        float2 p1 = {0.5f * facc2[nj][2], 0.5f * facc2[nj][3]};
        *(float2*)(g_pre + (size_t)((b * 64 + r0) * 64 + x) * 256 + n * 32 + d0) = p0;
        *(float2*)(g_pre + (size_t)((b * 64 + r0 + 8) * 64 + x) * 256 + n * 32 + d0) = p1;
    }
}

// out2: pre += 0.5*(qk_w @ v_h2) + lepe
#define O2_PHI 0
#define O2_PLO 9216
#define O2_VTHI 18432
#define O2_VTLO 23040
#define OUT2_SMEM 27648

__global__ __launch_bounds__(256) void out2_kernel(void)
{
    extern __shared__ char sm[];
    int blk = blockIdx.x;                 // (b*64 + y)*8 + n
    int n = blk & 7;
    int y = (blk >> 3) & 63;
    int b = blk >> 9;
    int tid = threadIdx.x, lane = tid & 31, wid = tid >> 5;
    uint32_t sbase = smem_u32(sm);

    const __nv_bfloat16* gh = g_qkwh + (size_t)blk * 4096;
    const __nv_bfloat16* gl = g_qkwl + (size_t)blk * 4096;
    for (int e = tid; e < 4096; e += 256) {
        int row = e >> 6, col = e & 63;
        *(__nv_bfloat16*)(sm + O2_PHI + (row * 72 + col) * 2) = gh[e];
        *(__nv_bfloat16*)(sm + O2_PLO + (row * 72 + col) * 2) = gl[e];
    }
    for (int e = tid; e < 2048; e += 256) {
        int j = e >> 5, d = e & 31;
        float vv = g_vh2[((size_t)((b * 64 + j) * 8 + n)) * 2048 + y * 32 + d];
        __nv_bfloat16 hh, ll;
        split1(vv, hh, ll);
        *(__nv_bfloat16*)(sm + O2_VTHI + (d * 72 + j) * 2) = hh;
        *(__nv_bfloat16*)(sm + O2_VTLO + (d * 72 + j) * 2) = ll;
    }
    __syncthreads();

    // PV (same tiling as pv_phase; P at O2_PHI/O2_PLO)
    int wm = wid >> 1, wn = wid & 1;
    uint32_t a_off = (uint32_t)((wm * 16 + (lane & 15)) * 72 + (((lane >> 4) & 1) << 3)) * 2;
    int m = lane >> 3;
    uint32_t b_off = (uint32_t)((wn * 16 + ((m >> 1) << 3) + (lane & 7)) * 72 + ((m & 1) << 3)) * 2;
    float facc[2][4];
#pragma unroll
    for (int nj = 0; nj < 2; nj++)
#pragma unroll
        for (int e = 0; e < 4; e++) facc[nj][e] = 0.f;
#pragma unroll
    for (int ks = 0; ks < 4; ks++) {
        uint32_t kb = (uint32_t)(ks * 16) * 2;
        uint32_t ah[4], al[4], bh[4], bl[4];
        ldm4(sbase + O2_PHI + a_off + kb, ah[0], ah[1], ah[2], ah[3]);
        ldm4(sbase + O2_PLO + a_off + kb, al[0], al[1], al[2], al[3]);
        ldm4(sbase + O2_VTHI + b_off + kb, bh[0], bh[1], bh[2], bh[3]);
        ldm4(sbase + O2_VTLO + b_off + kb, bl[0], bl[1], bl[2], bl[3]);
#pragma unroll
        for (int nj = 0; nj < 2; nj++) {
            int h2 = nj * 2;
            mma16816(facc[nj], ah, bh[h2], bh[h2 + 1]);
            mma16816(facc[nj], ah, bl[h2], bl[h2 + 1]);
            mma16816(facc[nj], al, bh[h2], bh[h2 + 1]);
        }
    }

#pragma unroll
    for (int nj = 0; nj < 2; nj++) {
        int r0 = wm * 16 + (lane >> 2);
        int d0 = wn * 16 + nj * 8 + ((lane & 3) << 1);
        size_t a0 = (size_t)((b * 64 + y) * 64 + r0) * 256 + n * 32 + d0;
        size_t a1 = (size_t)((b * 64 + y) * 64 + r0 + 8) * 256 + n * 32 + d0;
        float2 pr0 = *(float2*)(g_pre + a0);
        float2 le0 = *(float2*)(g_lepe + a0);
        float2 pr1 = *(float2*)(g_pre + a1);
        float2 le1 = *(float2*)(g_lepe + a1);
        float2 o0 = {pr0.x + 0.5f * facc[nj][0] + le0.x, pr0.y + 0.5f * facc[nj][1] + le0.y};
        float2 o1 = {pr1.x + 0.5f * facc[nj][2] + le1.x, pr1.y + 0.5f * facc[nj][3] + le1.y};
        *(float2*)(g_pre + a0) = o0;
        *(float2*)(g_pre + a1) = o1;
    }
}

// ---------------- launch ----------------
extern "C" void kernel_launch(void* const* d_in, const int* in_sizes, int n_in,
                              void* d_out, int out_size)
{
    const float* x    = (const float*)d_in[0];
    const float* sinp = (const float*)d_in[1];
    const float* cosp = (const float*)d_in[2];
    const float* Wq   = (const float*)d_in[3];
    const float* bq   = (const float*)d_in[4];
    const float* Wk   = (const float*)d_in[5];
    const float* bk   = (const float*)d_in[6];
    const float* Wv   = (const float*)d_in[7];
    const float* bv   = (const float*)d_in[8];
    const float* Wo   = (const float*)d_in[9];
    const float* bo   = (const float*)d_in[10];
    const float* lw   = (const float*)d_in[11];
    const float* lb   = (const float*)d_in[12];
    const float* dtw  = (const float*)d_in[13];
    const float* dtb  = (const float*)d_in[14];
    const float* Alog = (const float*)d_in[15];
    float* out = (float*)d_out;

    const float scaling = 0.17677669529663687f;   // 32^-0.5

    static int attr_set = 0;
    if (!attr_set) {
        cudaFuncSetAttribute(attn_w_kernel,
                             cudaFuncAttributeMaxDynamicSharedMemorySize, ATTN_SMEM);
        cudaFuncSetAttribute(attn_h_kernel,
                             cudaFuncAttributeMaxDynamicSharedMemorySize, ATTN_SMEM);
        cudaFuncSetAttribute(out2_kernel,
                             cudaFuncAttributeMaxDynamicSharedMemorySize, OUT2_SMEM);
        attr_set = 1;
    }

    dim3 gg(NROW / 128, 2);
    int convA_blocks = (NROW * Cn) / (256 * 4);   // 16384
    int convW_blocks = (Cn * Cn) / (256 * 4);     // 64

    convA_kernel<<<convA_blocks, 256>>>(x, 0);

    convW_kernel<<<convW_blocks, 256>>>(Wq);
    gemm_mma_kernel<<<gg, 256>>>(bq, nullptr, 0, 1.0f, sinp, cosp);
    convW_kernel<<<convW_blocks, 256>>>(Wk);
    gemm_mma_kernel<<<gg, 256>>>(bk, nullptr, 1, scaling, sinp, cosp);
    convW_kernel<<<convW_blocks, 256>>>(Wv);
    gemm_mma_kernel<<<gg, 256>>>(bv, nullptr, 2, 1.0f, sinp, cosp);

    dt_kernel<<<NROW, 256>>>(x, dtw, dtb, Alog);
    lepe_kernel<<<NROW, 256>>>(lw, lb);

    attn_w_kernel<<<Bn * Hn * Nn, 256, ATTN_SMEM>>>();
    attn_h_kernel<<<Bn * Wn * Nn, 256, ATTN_SMEM>>>();
    out2_kernel<<<Bn * Hn * Nn, 256, OUT2_SMEM>>>();

    convA_kernel<<<convA_blocks, 256>>>(nullptr, 1);
    convW_kernel<<<convW_blocks, 256>>>(Wo);
    gemm_mma_kernel<<<gg, 256>>>(bo, out, 3, 1.0f, sinp, cosp);
}

// round 7
// speedup vs baseline: 1.2009x; 1.2009x over previous
#include <cuda_runtime.h>
#include <cuda_bf16.h>
#include <math.h>
#include <stdint.h>

#define Bn 16
#define Hn 64
#define Wn 64
#define Cn 256
#define Nn 8
#define Dn 32
#define NROW (Bn*Hn*Wn)   // 65536

// ---------------- scratch (device globals; no allocation) ----------------
__device__ float g_q[NROW*Cn];
__device__ float g_k[NROW*Cn];
__device__ float g_v[NROW*Cn];
__device__ float g_lepe[NROW*Cn];
__device__ float g_pre[NROW*Cn];
__device__ float g_vw[Bn*Hn*Nn*64*32];       // [b][h][n][w][d]
__device__ float g_vh2[Bn*Wn*Nn*64*32];      // [b][w][n][h][d]
__device__ float g_da[Bn*Hn*Nn*Wn];          // [b][h][n][w]
__device__ float g_db[Bn*Wn*Nn*Hn];          // [b][w][n][h]
__device__ __nv_bfloat16 g_qkwh[Bn*Hn*Nn*4096];  // P hi  [b][h][n][i][j]
__device__ __nv_bfloat16 g_qkwl[Bn*Hn*Nn*4096];  // P lo

// bf16 hi/lo split buffers for projection GEMMs
__device__ __nv_bfloat16 g_ahi[NROW*Cn];
__device__ __nv_bfloat16 g_alo[NROW*Cn];
__device__ __nv_bfloat16 g_whi[4*Cn*Cn];
__device__ __nv_bfloat16 g_wlo[4*Cn*Cn];

// ---------------- helpers ----------------
__device__ __forceinline__ uint32_t smem_u32(const void* p) {
    uint32_t a;
    asm("{ .reg .u64 t; cvta.to.shared.u64 t, %1; cvt.u32.u64 %0, t; }"
        : "=r"(a) : "l"(p));
    return a;
}

__device__ __forceinline__ uint32_t pack_bf2(float a, float b) {
    return (uint32_t)__bfloat16_as_ushort(__float2bfloat16_rn(a))
         | ((uint32_t)__bfloat16_as_ushort(__float2bfloat16_rn(b)) << 16);
}

__device__ __forceinline__ void split4(float4 a, uint2& hv, uint2& lv) {
    float h0 = __bfloat162float(__float2bfloat16_rn(a.x));
    float h1 = __bfloat162float(__float2bfloat16_rn(a.y));
    float h2 = __bfloat162float(__float2bfloat16_rn(a.z));
    float h3 = __bfloat162float(__float2bfloat16_rn(a.w));
    hv.x = pack_bf2(a.x, a.y);
    hv.y = pack_bf2(a.z, a.w);
    lv.x = pack_bf2(a.x - h0, a.y - h1);
    lv.y = pack_bf2(a.z - h2, a.w - h3);
}

__device__ __forceinline__ void split1(float v, __nv_bfloat16& h, __nv_bfloat16& l) {
    h = __float2bfloat16_rn(v);
    l = __float2bfloat16_rn(v - __bfloat162float(h));
}

__device__ __forceinline__ void ldm4(uint32_t addr, uint32_t& r0, uint32_t& r1,
                                     uint32_t& r2, uint32_t& r3) {
    asm volatile("ldmatrix.sync.aligned.m8n8.x4.shared.b16 {%0,%1,%2,%3}, [%4];"
                 : "=r"(r0), "=r"(r1), "=r"(r2), "=r"(r3) : "r"(addr));
}

__device__ __forceinline__ void ldm4t(uint32_t addr, uint32_t& r0, uint32_t& r1,
                                      uint32_t& r2, uint32_t& r3) {
    asm volatile("ldmatrix.sync.aligned.m8n8.x4.trans.shared.b16 {%0,%1,%2,%3}, [%4];"
                 : "=r"(r0), "=r"(r1), "=r"(r2), "=r"(r3) : "r"(addr));
}

__device__ __forceinline__ void mma16816(float* d, const uint32_t* a,
                                         uint32_t b0, uint32_t b1) {
    asm volatile("mma.sync.aligned.m16n8k16.row.col.f32.bf16.bf16.f32 "
                 "{%0,%1,%2,%3}, {%4,%5,%6,%7}, {%8,%9}, {%0,%1,%2,%3};"
                 : "+f"(d[0]), "+f"(d[1]), "+f"(d[2]), "+f"(d[3])
                 : "r"(a[0]), "r"(a[1]), "r"(a[2]), "r"(a[3]), "r"(b0), "r"(b1));
}

#define CPA16(dst, src) \
    asm volatile("cp.async.cg.shared.global [%0], [%1], 16;" \
                 :: "r"(dst), "l"(src) : "memory")

// ------------- conversion passes: fp32 -> bf16 hi/lo -------------
__global__ __launch_bounds__(256) void convA_kernel(const float* __restrict__ srcExt, int sel)
{
    const float* src = (sel == 0) ? srcExt : g_pre;
    size_t i = ((size_t)blockIdx.x * 256 + threadIdx.x) * 4;
    float4 v = *(const float4*)(src + i);
    uint2 hv, lv; split4(v, hv, lv);
    *(uint2*)(g_ahi + i) = hv;
    *(uint2*)(g_alo + i) = lv;
}

__global__ __launch_bounds__(256) void convW_kernel(
    const float* __restrict__ wq, const float* __restrict__ wk,
    const float* __restrict__ wv, const float* __restrict__ wo)
{
    const float* src = (blockIdx.y == 0) ? wq : (blockIdx.y == 1) ? wk
                     : (blockIdx.y == 2) ? wv : wo;
    size_t base = (size_t)blockIdx.y * 65536;
    size_t i = ((size_t)blockIdx.x * 256 + threadIdx.x) * 4;
    float4 v = *(const float4*)(src + i);
    uint2 hv, lv; split4(v, hv, lv);
    *(uint2*)(g_whi + base + i) = hv;
    *(uint2*)(g_wlo + base + i) = lv;
}

// ------------- projection GEMM (mma.sync bf16 hi/lo, cp.async double buffer) -------------
#define GP 40       // smem pitch (bf16 elems)
#define GMAT 10240  // bytes per matrix (128*GP*2)
#define GSTG 40960  // bytes per stage (4 matrices)
#define GEMM_SMEM (2*GSTG)

__global__ __launch_bounds__(256) void gemm_mma_kernel(
    const float* __restrict__ bias, float* __restrict__ dout,
    int dst_sel, float scale,
    const float* __restrict__ sinp, const float* __restrict__ cosp)
{
    extern __shared__ char gsm[];
    float* outp = (dst_sel == 0) ? g_q : (dst_sel == 1) ? g_k
                : (dst_sel == 2) ? g_v : dout;
    const bool do_rope = (dst_sel <= 1);
    const __nv_bfloat16* Whi = g_whi + (size_t)dst_sel * 65536;
    const __nv_bfloat16* Wlo = g_wlo + (size_t)dst_sel * 65536;

    int tid = threadIdx.x;
    int lane = tid & 31, wid = tid >> 5;
    int warp_m = wid >> 2, warp_n = wid & 3;
    int row0 = blockIdx.x * 128;
    int n0 = blockIdx.y * 128;

    int r0i = tid >> 2, q0 = tid & 3;
    int r1i = (tid + 256) >> 2, q1 = tid & 3;
    uint32_t st0 = (uint32_t)(r0i * GP + q0 * 8) * 2;
    uint32_t st1 = (uint32_t)(r1i * GP + q1 * 8) * 2;
    uint32_t gsb = smem_u32(gsm);

    float acc[4][4][4];
#pragma unroll
    for (int i = 0; i < 4; i++)
#pragma unroll
        for (int j = 0; j < 4; j++)
#pragma unroll
            for (int e = 0; e < 4; e++) acc[i][j][e] = 0.f;

    // fragment smem byte offsets (within a matrix)
    uint32_t a_off[4], b_off[2];
#pragma unroll
    for (int mi = 0; mi < 4; mi++) {
        int row = warp_m * 64 + mi * 16 + (lane & 15);
        int col = ((lane >> 4) & 1) << 3;
        a_off[mi] = (uint32_t)(row * GP + col) * 2;
    }
#pragma unroll
    for (int p = 0; p < 2; p++) {
        int m = lane >> 3;
        int nrow = warp_n * 32 + p * 16 + ((m >> 1) << 3) + (lane & 7);
        int col = (m & 1) << 3;
        b_off[p] = (uint32_t)(nrow * GP + col) * 2;
    }

    // issue stage kc
    auto issue = [&](int kc) {
        uint32_t sb = gsb + (kc & 1) * GSTG;
        int kn = kc * 32;
        size_t a0 = (size_t)(row0 + r0i) * 256 + kn + q0 * 8;
        size_t a1 = (size_t)(row0 + r1i) * 256 + kn + q1 * 8;
        size_t b0 = (size_t)(n0 + r0i) * 256 + kn + q0 * 8;
        size_t b1 = (size_t)(n0 + r1i) * 256 + kn + q1 * 8;
        CPA16(sb + 0*GMAT + st0, (const void*)(g_ahi + a0));
        CPA16(sb + 0*GMAT + st1, (const void*)(g_ahi + a1));
        CPA16(sb + 1*GMAT + st0, (const void*)(g_alo + a0));
        CPA16(sb + 1*GMAT + st1, (const void*)(g_alo + a1));
        CPA16(sb + 2*GMAT + st0, (const void*)(Whi + b0));
        CPA16(sb + 2*GMAT + st1, (const void*)(Whi + b1));
        CPA16(sb + 3*GMAT + st0, (const void*)(Wlo + b0));
        CPA16(sb + 3*GMAT + st1, (const void*)(Wlo + b1));
        asm volatile("cp.async.commit_group;" ::: "memory");
    };

    issue(0);
    for (int kc = 0; kc < 8; kc++) {
        if (kc < 7) {
            issue(kc + 1);
            asm volatile("cp.async.wait_group 1;" ::: "memory");
        } else {
            asm volatile("cp.async.wait_group 0;" ::: "memory");
        }
        __syncthreads();
        uint32_t sb = gsb + (kc & 1) * GSTG;
#pragma unroll
        for (int ks = 0; ks < 2; ks++) {
            uint32_t kb = (uint32_t)(ks * 16) * 2;
            uint32_t ah[4][4], al[4][4], bh[2][4], bl[2][4];
#pragma unroll
            for (int mi = 0; mi < 4; mi++) {
                ldm4(sb + 0*GMAT + a_off[mi] + kb, ah[mi][0], ah[mi][1], ah[mi][2], ah[mi][3]);
                ldm4(sb + 1*GMAT + a_off[mi] + kb, al[mi][0], al[mi][1], al[mi][2], al[mi][3]);
            }
#pragma unroll
            for (int p = 0; p < 2; p++) {
                ldm4(sb + 2*GMAT + b_off[p] + kb, bh[p][0], bh[p][1], bh[p][2], bh[p][3]);
                ldm4(sb + 3*GMAT + b_off[p] + kb, bl[p][0], bl[p][1], bl[p][2], bl[p][3]);
            }
#pragma unroll
            for (int mi = 0; mi < 4; mi++) {
#pragma unroll
                for (int nj = 0; nj < 4; nj++) {
                    int p = nj >> 1, h = (nj & 1) << 1;
                    mma16816(acc[mi][nj], ah[mi], bh[p][h], bh[p][h + 1]);
                    mma16816(acc[mi][nj], ah[mi], bl[p][h], bl[p][h + 1]);
                    mma16816(acc[mi][nj], al[mi], bh[p][h], bh[p][h + 1]);
                }
            }
        }
        __syncthreads();
    }

    // epilogue: bias + scale (+ rope for q/k), fp32 store
#pragma unroll
    for (int mi = 0; mi < 4; mi++) {
        int rbase = row0 + warp_m * 64 + mi * 16 + (lane >> 2);
        int hw0 = rbase & 4095;
        int hw8 = (rbase + 8) & 4095;
#pragma unroll
        for (int nj = 0; nj < 4; nj++) {
            int c = n0 + warp_n * 32 + nj * 8 + ((lane & 3) << 1);
            float b0 = __ldg(bias + c), b1 = __ldg(bias + c + 1);
            float2 o0, o1;
            o0.x = (acc[mi][nj][0] + b0) * scale;
            o0.y = (acc[mi][nj][1] + b1) * scale;
            o1.x = (acc[mi][nj][2] + b0) * scale;
            o1.y = (acc[mi][nj][3] + b1) * scale;
            if (do_rope) {
                int d0 = c & 31;
                float s0 = __ldg(sinp + hw0 * 32 + d0);
                float s1 = __ldg(sinp + hw0 * 32 + d0 + 1);
                float c0v = __ldg(cosp + hw0 * 32 + d0);
                float c1v = __ldg(cosp + hw0 * 32 + d0 + 1);
                float xe = o0.x, xo = o0.y;
                o0.x = xe * c0v - xo * s0;
                o0.y = xo * c1v + xe * s1;
                float s0b = __ldg(sinp + hw8 * 32 + d0);
                float s1b = __ldg(sinp + hw8 * 32 + d0 + 1);
                float c0b = __ldg(cosp + hw8 * 32 + d0);
                float c1b = __ldg(cosp + hw8 * 32 + d0 + 1);
                float xe1 = o1.x, xo1 = o1.y;
                o1.x = xe1 * c0b - xo1 * s0b;
                o1.y = xo1 * c1b + xe1 * s1b;
            }
            *(float2*)(outp + (size_t)rbase * 256 + c) = o0;
            *(float2*)(outp + (size_t)(rbase + 8) * 256 + c) = o1;
        }
    }
}

// ---------------- dt -> da/db ----------------
__device__ __forceinline__ float softplusf(float a) {
    return (a > 20.f) ? a : log1pf(expf(a));
}

__global__ __launch_bounds__(256) void dt_kernel(
    const float* __restrict__ x, const float* __restrict__ dtw,
    const float* __restrict__ dtb, const float* __restrict__ Alog)
{
    int r = blockIdx.x;
    int w = r & 63;
    int h = (r >> 6) & 63;
    int b = r >> 12;
    int c = threadIdx.x;
    int n = c >> 5, d = c & 31;

    float xv = x[r * 256 + c];
    float t0 = xv * dtw[d];
    float t1 = xv * dtw[32 + d];
#pragma unroll
    for (int off = 16; off; off >>= 1) {
        t0 += __shfl_down_sync(0xffffffffu, t0, off);
        t1 += __shfl_down_sync(0xffffffffu, t1, off);
    }
    if (d == 0) {
        float bias = dtb[n];
        float Aa = -expf(Alog[n]);
        float da = softplusf(t0 + bias) * Aa;
        float db = softplusf(t1 + bias) * Aa;
        g_da[((b * 64 + h) * 8 + n) * 64 + w] = da;
        g_db[((b * 64 + w) * 8 + n) * 64 + h] = db;
    }
}

// ---------------- LePE depthwise 5x5 conv ----------------
__global__ __launch_bounds__(256) void lepe_kernel(
    const float* __restrict__ lw, const float* __restrict__ lb)
{
    int r = blockIdx.x;
    int w = r & 63, h = (r >> 6) & 63, b = r >> 12;
    int c = threadIdx.x;
    float acc = lb[c];
#pragma unroll
    for (int ki = 0; ki < 5; ki++) {
        int hh = h + ki - 2;
        if ((unsigned)hh >= 64u) continue;
#pragma unroll
        for (int kj = 0; kj < 5; kj++) {
            int ww = w + kj - 2;
            if ((unsigned)ww >= 64u) continue;
            acc += __ldg(&g_v[((b * 64 + hh) * 64 + ww) * 256 + c]) * lw[(ki * 5 + kj) * 256 + c];
        }
    }
    g_lepe[r * 256 + c] = acc;
}

// ---------------- attention (mma.sync bf16 hi/lo; trans-ldmatrix B) ----------------
// smem layout (bytes). q/k/v/w row-major pitch 40; P pitch 72; S fp32 pitch 66.
#define AT_QHI 0
#define AT_QLO 5120
#define AT_KHI 10240
#define AT_KLO 15360
#define AT_VHI 20480
#define AT_VLO 25600
#define AT_WHI 30720
#define AT_WLO 35840
#define AT_PHI 0          // overlays q/k region after S phase
#define AT_PLO 9216
// attn_w: S right after V
#define AT_SW  30720
#define AT_CSW 47616
#define ATTN_SMEM_W 47872
// attn_h: S after W
#define AT_SH  40960
#define AT_CSH 57856
#define ATTN_SMEM_H 58112

// S = QK^T (+mask). 8 warps: wm=wid>>2 (32 rows), wn=wid&3 (16 cols).
__device__ __forceinline__ void s_phase(uint32_t sbase, int lane, int wid,
                                        float* S, const float* cs)
{
    int wm = wid >> 2, wn = wid & 3;
    uint32_t a_off[2];
#pragma unroll
    for (int mi = 0; mi < 2; mi++) {
        int row = wm * 32 + mi * 16 + (lane & 15);
        int col = ((lane >> 4) & 1) << 3;
        a_off[mi] = (uint32_t)(row * GP + col) * 2;
    }
    int m = lane >> 3;
    uint32_t b_off = (uint32_t)((wn * 16 + ((m >> 1) << 3) + (lane & 7)) * GP + ((m & 1) << 3)) * 2;

    float sacc[2][2][4];
#pragma unroll
    for (int a = 0; a < 2; a++)
#pragma unroll
        for (int b2 = 0; b2 < 2; b2++)
#pragma unroll
            for (int e = 0; e < 4; e++) sacc[a][b2][e] = 0.f;

#pragma unroll
    for (int ks = 0; ks < 2; ks++) {
        uint32_t kb = (uint32_t)(ks * 16) * 2;
        uint32_t ah[2][4], al[2][4], bh[4], bl[4];
#pragma unroll
        for (int mi = 0; mi < 2; mi++) {
            ldm4(sbase + AT_QHI + a_off[mi] + kb, ah[mi][0], ah[mi][1], ah[mi][2], ah[mi][3]);
            ldm4(sbase + AT_QLO + a_off[mi] + kb, al[mi][0], al[mi][1], al[mi][2], al[mi][3]);
        }
        ldm4(sbase + AT_KHI + b_off + kb, bh[0], bh[1], bh[2], bh[3]);
        ldm4(sbase + AT_KLO + b_off + kb, bl[0], bl[1], bl[2], bl[3]);
#pragma unroll
        for (int mi = 0; mi < 2; mi++) {
#pragma unroll
            for (int nj = 0; nj < 2; nj++) {
                int h2 = nj * 2;
                mma16816(sacc[mi][nj], ah[mi], bh[h2], bh[h2 + 1]);
                mma16816(sacc[mi][nj], ah[mi], bl[h2], bl[h2 + 1]);
                mma16816(sacc[mi][nj], al[mi], bh[h2], bh[h2 + 1]);
            }
        }
    }
#pragma unroll
    for (int mi = 0; mi < 2; mi++) {
#pragma unroll
        for (int nj = 0; nj < 2; nj++) {
            int r0 = wm * 32 + mi * 16 + (lane >> 2);
            int c0 = wn * 16 + nj * 8 + ((lane & 3) << 1);
            float cr0 = cs[r0], cr8 = cs[r0 + 8];
            float cc0 = cs[c0], cc1 = cs[c0 + 1];
            S[r0 * 66 + c0]       = sacc[mi][nj][0] + ((r0 >= c0)     ? cr0 - cc0 : cc0 - cr0);
            S[r0 * 66 + c0 + 1]   = sacc[mi][nj][1] + ((r0 >= c0 + 1) ? cr0 - cc1 : cc1 - cr0);
            S[(r0 + 8) * 66 + c0]     = sacc[mi][nj][2] + ((r0 + 8 >= c0)     ? cr8 - cc0 : cc0 - cr8);
            S[(r0 + 8) * 66 + c0 + 1] = sacc[mi][nj][3] + ((r0 + 8 >= c0 + 1) ? cr8 - cc1 : cc1 - cr8);
        }
    }
}

// softmax on S rows -> bf16 hi/lo P in smem (pitch 72)
__device__ __forceinline__ void softmax_phase(char* sm, int lane, int wid, float* S)
{
#pragma unroll
    for (int rr = 0; rr < 8; rr++) {
        int i = wid * 8 + rr;
        float v0 = S[i * 66 + lane], v1 = S[i * 66 + lane + 32];
        float mx = fmaxf(v0, v1);
#pragma unroll
        for (int off = 16; off; off >>= 1) mx = fmaxf(mx, __shfl_xor_sync(0xffffffffu, mx, off));
        float e0 = __expf(v0 - mx), e1 = __expf(v1 - mx);
        float s = e0 + e1;
#pragma unroll
        for (int off = 16; off; off >>= 1) s += __shfl_xor_sync(0xffffffffu, s, off);
        float inv = 1.f / s;
        float p0 = e0 * inv, p1 = e1 * inv;
        __nv_bfloat16 h0, l0, h1, l1;
        split1(p0, h0, l0);
        split1(p1, h1, l1);
        *(__nv_bfloat16*)(sm + AT_PHI + (i * 72 + lane) * 2) = h0;
        *(__nv_bfloat16*)(sm + AT_PHI + (i * 72 + lane + 32) * 2) = h1;
        *(__nv_bfloat16*)(sm + AT_PLO + (i * 72 + lane) * 2) = l0;
        *(__nv_bfloat16*)(sm + AT_PLO + (i * 72 + lane + 32) * 2) = l1;
    }
}

// PV: per warp 16x16 tile of P(64x64) @ V(64x32) with V row-major + trans ldmatrix
__device__ __forceinline__ void pv_phase(uint32_t sbase, int lane, int wid,
                                         uint32_t bhi, uint32_t blo, float facc[2][4])
{
    int wm = wid >> 1, wn = wid & 1;
    uint32_t a_off = (uint32_t)((wm * 16 + (lane & 15)) * 72 + (((lane >> 4) & 1) << 3)) * 2;
    int g = lane >> 3, j8 = lane & 7;
    uint32_t b_off = (uint32_t)(((g & 1) * 8 + j8) * GP + wn * 16 + ((g >> 1) << 3)) * 2;
#pragma unroll
    for (int ks = 0; ks < 4; ks++) {
        uint32_t kbA = (uint32_t)(ks * 16) * 2;
        uint32_t kbB = (uint32_t)(ks * 16 * GP) * 2;
        uint32_t ah[4], al[4], bh[4], bl[4];
        ldm4(sbase + AT_PHI + a_off + kbA, ah[0], ah[1], ah[2], ah[3]);
        ldm4(sbase + AT_PLO + a_off + kbA, al[0], al[1], al[2], al[3]);
        ldm4t(bhi + b_off + kbB, bh[0], bh[1], bh[2], bh[3]);
        ldm4t(blo + b_off + kbB, bl[0], bl[1], bl[2], bl[3]);
#pragma unroll
        for (int nj = 0; nj < 2; nj++) {
            int h2 = nj * 2;
            mma16816(facc[nj], ah, bh[h2], bh[h2 + 1]);
            mma16816(facc[nj], ah, bl[h2], bl[h2 + 1]);
            mma16816(facc[nj], al, bh[h2], bh[h2 + 1]);
        }
    }
}

__global__ __launch_bounds__(256) void attn_w_kernel(void)
{
    extern __shared__ char sm[];
    int blk = blockIdx.x;                 // (b*64 + h)*8 + n
    int n = blk & 7;
    int h = (blk >> 3) & 63;
    int b = blk >> 9;
    int tid = threadIdx.x, lane = tid & 31, wid = tid >> 5;
    int qbase = ((b * 64 + h) * 64) * 256 + n * 32;
    float* S = (float*)(sm + AT_SW);
    float* cs = (float*)(sm + AT_CSW);
    uint32_t sbase = smem_u32(sm);

    for (int e = tid; e < 512; e += 256) {
        int i = e >> 3, d4 = (e & 7) << 2;
        float4 qv = *(const float4*)(g_q + qbase + i * 256 + d4);
        float4 kv = *(const float4*)(g_k + qbase + i * 256 + d4);
        float4 vv = *(const float4*)(g_v + qbase + i * 256 + d4);
        uint2 hv, lv;
        uint32_t so = (uint32_t)(i * GP + d4) * 2;
        split4(qv, hv, lv);
        *(uint2*)(sm + AT_QHI + so) = hv; *(uint2*)(sm + AT_QLO + so) = lv;
        split4(kv, hv, lv);
        *(uint2*)(sm + AT_KHI + so) = hv; *(uint2*)(sm + AT_KLO + so) = lv;
        split4(vv, hv, lv);
        *(uint2*)(sm + AT_VHI + so) = hv; *(uint2*)(sm + AT_VLO + so) = lv;
    }
    if (tid == 0) {
        float run = 0.f;
        const float* dap = g_da + blk * 64;
        for (int j = 0; j < 64; j++) { run += dap[j]; cs[j] = run; }
    }
    __syncthreads();

    s_phase(sbase, lane, wid, S, cs);
    __syncthreads();

    softmax_phase(sm, lane, wid, S);
    __syncthreads();

    // vectorized P store for out2 reuse
    __nv_bfloat16* gh = g_qkwh + (size_t)blk * 4096;
    __nv_bfloat16* gl = g_qkwl + (size_t)blk * 4096;
    for (int e = tid; e < 512; e += 256) {
        int row = e >> 3, c8 = (e & 7) << 3;
        *(uint4*)(gh + row * 64 + c8) = *(uint4*)(sm + AT_PHI + (row * 72 + c8) * 2);
        *(uint4*)(gl + row * 64 + c8) = *(uint4*)(sm + AT_PLO + (row * 72 + c8) * 2);
    }

    float facc[2][4];
#pragma unroll
    for (int nj = 0; nj < 2; nj++)
#pragma unroll
        for (int e = 0; e < 4; e++) facc[nj][e] = 0.f;
    pv_phase(sbase, lane, wid, sbase + AT_VHI, sbase + AT_VLO, facc);

    float* vwp = g_vw + (size_t)blk * 2048;
    int wm = wid >> 1, wn = wid & 1;
#pragma unroll
    for (int nj = 0; nj < 2; nj++) {
        int r0 = wm * 16 + (lane >> 2);
        int d0 = wn * 16 + nj * 8 + ((lane & 3) << 1);
        float2 o0 = {facc[nj][0], facc[nj][1]};
        float2 o1 = {facc[nj][2], facc[nj][3]};
        *(float2*)(vwp + r0 * 32 + d0) = o0;
        *(float2*)(vwp + (r0 + 8) * 32 + d0) = o1;
    }
}

__global__ __launch_bounds__(256) void attn_h_kernel(void)
{
    extern __shared__ char sm[];
    int blk = blockIdx.x;                 // (b*64 + x)*8 + n
    int n = blk & 7;
    int x = (blk >> 3) & 63;
    int b = blk >> 9;
    int tid = threadIdx.x, lane = tid & 31, wid = tid >> 5;
    int qbase = (b * 64 * 64 + x) * 256 + n * 32;
    float* S = (float*)(sm + AT_SH);
    float* cs = (float*)(sm + AT_CSH);
    uint32_t sbase = smem_u32(sm);

    for (int e = tid; e < 512; e += 256) {
        int i = e >> 3, d4 = (e & 7) << 2;
        float4 qv = *(const float4*)(g_q + qbase + i * 16384 + d4);
        float4 kv = *(const float4*)(g_k + qbase + i * 16384 + d4);
        float4 vv = *(const float4*)(g_v + qbase + i * 16384 + d4);
        float4 wv = *(const float4*)(g_vw + ((size_t)((b * 64 + i) * 8 + n)) * 2048 + x * 32 + d4);
        uint2 hv, lv;
        uint32_t so = (uint32_t)(i * GP + d4) * 2;
        split4(qv, hv, lv);
        *(uint2*)(sm + AT_QHI + so) = hv; *(uint2*)(sm + AT_QLO + so) = lv;
        split4(kv, hv, lv);
        *(uint2*)(sm + AT_KHI + so) = hv; *(uint2*)(sm + AT_KLO + so) = lv;
        split4(vv, hv, lv);
        *(uint2*)(sm + AT_VHI + so) = hv; *(uint2*)(sm + AT_VLO + so) = lv;
        split4(wv, hv, lv);
        *(uint2*)(sm + AT_WHI + so) = hv; *(uint2*)(sm + AT_WLO + so) = lv;
    }
    if (tid == 0) {
        float run = 0.f;
        const float* dbp = g_db + blk * 64;
        for (int j = 0; j < 64; j++) { run += dbp[j]; cs[j] = run; }
    }
    __syncthreads();

    s_phase(sbase, lane, wid, S, cs);
    __syncthreads();

    softmax_phase(sm, lane, wid, S);
    __syncthreads();

    float facc1[2][4], facc2[2][4];
#pragma unroll
    for (int nj = 0; nj < 2; nj++)
#pragma unroll
        for (int e = 0; e < 4; e++) { facc1[nj][e] = 0.f; facc2[nj][e] = 0.f; }
    pv_phase(sbase, lane, wid, sbase + AT_VHI, sbase + AT_VLO, facc1);
    pv_phase(sbase, lane, wid, sbase + AT_WHI, sbase + AT_WLO, facc2);

    float* v2p = g_vh2 + (size_t)blk * 2048;
    int wm = wid >> 1, wn = wid & 1;
#pragma unroll
    for (int nj = 0; nj < 2; nj++) {
        int r0 = wm * 16 + (lane >> 2);
        int d0 = wn * 16 + nj * 8 + ((lane & 3) << 1);
        float2 o0 = {facc1[nj][0], facc1[nj][1]};
        float2 o1 = {facc1[nj][2], facc1[nj][3]};
        *(float2*)(v2p + r0 * 32 + d0) = o0;
        *(float2*)(v2p + (r0 + 8) * 32 + d0) = o1;
        float2 p0 = {0.5f * facc2[nj][0], 0.5f * facc2[nj][1]};
        float2 p1 = {0.5f * facc2[nj][2], 0.5f * facc2[nj][3]};
        *(float2*)(g_pre + (size_t)((b * 64 + r0) * 64 + x) * 256 + n * 32 + d0) = p0;
        *(float2*)(g_pre + (size_t)((b * 64 + r0 + 8) * 64 + x) * 256 + n * 32 + d0) = p1;
    }
}

// out2: pre += 0.5*(qk_w @ v_h2) + lepe
#define O2_PHI 0
#define O2_PLO 9216
#define O2_VHI 18432
#define O2_VLO 23552
#define OUT2_SMEM 28672

__global__ __launch_bounds__(256) void out2_kernel(void)
{
    extern __shared__ char sm[];
    int blk = blockIdx.x;                 // (b*64 + y)*8 + n
    int n = blk & 7;
    int y = (blk >> 3) & 63;
    int b = blk >> 9;
    int tid = threadIdx.x, lane = tid & 31, wid = tid >> 5;
    uint32_t sbase = smem_u32(sm);

    const __nv_bfloat16* gh = g_qkwh + (size_t)blk * 4096;
    const __nv_bfloat16* gl = g_qkwl + (size_t)blk * 4096;
    for (int e = tid; e < 512; e += 256) {
        int row = e >> 3, c8 = (e & 7) << 3;
        *(uint4*)(sm + O2_PHI + (row * 72 + c8) * 2) = *(const uint4*)(gh + row * 64 + c8);
        *(uint4*)(sm + O2_PLO + (row * 72 + c8) * 2) = *(const uint4*)(gl + row * 64 + c8);
    }
    for (int e = tid; e < 512; e += 256) {
        int j = e >> 3, d4 = (e & 7) << 2;
        float4 vv = *(const float4*)(g_vh2 + ((size_t)((b * 64 + j) * 8 + n)) * 2048 + y * 32 + d4);
        uint2 hv, lv;
        split4(vv, hv, lv);
        uint32_t so = (uint32_t)(j * GP + d4) * 2;
        *(uint2*)(sm + O2_VHI + so) = hv;
        *(uint2*)(sm + O2_VLO + so) = lv;
    }
    __syncthreads();

    int wm = wid >> 1, wn = wid & 1;
    uint32_t a_off = (uint32_t)((wm * 16 + (lane & 15)) * 72 + (((lane >> 4) & 1) << 3)) * 2;
    int g = lane >> 3, j8 = lane & 7;
    uint32_t b_off = (uint32_t)(((g & 1) * 8 + j8) * GP + wn * 16 + ((g >> 1) << 3)) * 2;
    float facc[2][4];
#pragma unroll
    for (int nj = 0; nj < 2; nj++)
#pragma unroll
        for (int e = 0; e < 4; e++) facc[nj][e] = 0.f;
#pragma unroll
    for (int ks = 0; ks < 4; ks++) {
        uint32_t kbA = (uint32_t)(ks * 16) * 2;
        uint32_t kbB = (uint32_t)(ks * 16 * GP) * 2;
        uint32_t ah[4], al[4], bh[4], bl[4];
        ldm4(sbase + O2_PHI + a_off + kbA, ah[0], ah[1], ah[2], ah[3]);
        ldm4(sbase + O2_PLO + a_off + kbA, al[0], al[1], al[2], al[3]);
        ldm4t(sbase + O2_VHI + b_off + kbB, bh[0], bh[1], bh[2], bh[3]);
        ldm4t(sbase + O2_VLO + b_off + kbB, bl[0], bl[1], bl[2], bl[3]);
#pragma unroll
        for (int nj = 0; nj < 2; nj++) {
            int h2 = nj * 2;
            mma16816(facc[nj], ah, bh[h2], bh[h2 + 1]);
            mma16816(facc[nj], ah, bl[h2], bl[h2 + 1]);
            mma16816(facc[nj], al, bh[h2], bh[h2 + 1]);
        }
    }

#pragma unroll
    for (int nj = 0; nj < 2; nj++) {
        int r0 = wm * 16 + (lane >> 2);
        int d0 = wn * 16 + nj * 8 + ((lane & 3) << 1);
        size_t a0 = (size_t)((b * 64 + y) * 64 + r0) * 256 + n * 32 + d0;
        size_t a1 = (size_t)((b * 64 + y) * 64 + r0 + 8) * 256 + n * 32 + d0;
        float2 pr0 = *(float2*)(g_pre + a0);
        float2 le0 = *(float2*)(g_lepe + a0);
        float2 pr1 = *(float2*)(g_pre + a1);
        float2 le1 = *(float2*)(g_lepe + a1);
        float2 o0 = {pr0.x + 0.5f * facc[nj][0] + le0.x, pr0.y + 0.5f * facc[nj][1] + le0.y};
        float2 o1 = {pr1.x + 0.5f * facc[nj][2] + le1.x, pr1.y + 0.5f * facc[nj][3] + le1.y};
        *(float2*)(g_pre + a0) = o0;
        *(float2*)(g_pre + a1) = o1;
    }
}

// ---------------- launch ----------------
extern "C" void kernel_launch(void* const* d_in, const int* in_sizes, int n_in,
                              void* d_out, int out_size)
{
    const float* x    = (const float*)d_in[0];
    const float* sinp = (const float*)d_in[1];
    const float* cosp = (const float*)d_in[2];
    const float* Wq   = (const float*)d_in[3];
    const float* bq   = (const float*)d_in[4];
    const float* Wk   = (const float*)d_in[5];
    const float* bk   = (const float*)d_in[6];
    const float* Wv   = (const float*)d_in[7];
    const float* bv   = (const float*)d_in[8];
    const float* Wo   = (const float*)d_in[9];
    const float* bo   = (const float*)d_in[10];
    const float* lw   = (const float*)d_in[11];
    const float* lb   = (const float*)d_in[12];
    const float* dtw  = (const float*)d_in[13];
    const float* dtb  = (const float*)d_in[14];
    const float* Alog = (const float*)d_in[15];
    float* out = (float*)d_out;

    const float scaling = 0.17677669529663687f;   // 32^-0.5

    cudaFuncSetAttribute(gemm_mma_kernel,
                         cudaFuncAttributeMaxDynamicSharedMemorySize, GEMM_SMEM);
    cudaFuncSetAttribute(attn_w_kernel,
                         cudaFuncAttributeMaxDynamicSharedMemorySize, ATTN_SMEM_W);
    cudaFuncSetAttribute(attn_h_kernel,
                         cudaFuncAttributeMaxDynamicSharedMemorySize, ATTN_SMEM_H);
    cudaFuncSetAttribute(out2_kernel,
                         cudaFuncAttributeMaxDynamicSharedMemorySize, OUT2_SMEM);

    dim3 gg(NROW / 128, 2);
    int convA_blocks = (NROW * Cn) / (256 * 4);   // 16384

    convA_kernel<<<convA_blocks, 256>>>(x, 0);                        // 0
    convW_kernel<<<dim3(64, 4), 256>>>(Wq, Wk, Wv, Wo);               // 1
    dt_kernel<<<NROW, 256>>>(x, dtw, dtb, Alog);                      // 2

    gemm_mma_kernel<<<gg, 256, GEMM_SMEM>>>(bq, nullptr, 0, 1.0f, sinp, cosp);    // 3
    gemm_mma_kernel<<<gg, 256, GEMM_SMEM>>>(bk, nullptr, 1, scaling, sinp, cosp); // 4
    gemm_mma_kernel<<<gg, 256, GEMM_SMEM>>>(bv, nullptr, 2, 1.0f, sinp, cosp);    // 5 <- profiled

    lepe_kernel<<<NROW, 256>>>(lw, lb);                               // 6

    attn_w_kernel<<<Bn * Hn * Nn, 256, ATTN_SMEM_W>>>();              // 7
    attn_h_kernel<<<Bn * Wn * Nn, 256, ATTN_SMEM_H>>>();              // 8
    out2_kernel<<<Bn * Hn * Nn, 256, OUT2_SMEM>>>();                  // 9

    convA_kernel<<<convA_blocks, 256>>>(nullptr, 1);                  // 10
    gemm_mma_kernel<<<gg, 256, GEMM_SMEM>>>(bo, out, 3, 1.0f, sinp, cosp);        // 11
}

// round 9
// speedup vs baseline: 1.4825x; 1.2345x over previous
#include <cuda_runtime.h>
#include <cuda_bf16.h>
#include <math.h>
#include <stdint.h>

#define Bn 16
#define Hn 64
#define Wn 64
#define Cn 256
#define Nn 8
#define Dn 32
#define NROW (Bn*Hn*Wn)   // 65536

// ---------------- scratch (device globals; no allocation) ----------------
__device__ float g_q[NROW*Cn];
__device__ float g_k[NROW*Cn];
__device__ float g_v[NROW*Cn];
__device__ float g_lepe[NROW*Cn];
__device__ float g_pre[NROW*Cn];
__device__ float g_vw[Bn*Hn*Nn*64*32];       // [b][h][n][w][d]
__device__ float g_vh2[Bn*Wn*Nn*64*32];      // [b][w][n][h][d]
__device__ float g_da[Bn*Hn*Nn*Wn];          // [b][h][n][w]
__device__ float g_db[Bn*Wn*Nn*Hn];          // [b][w][n][h]
__device__ __nv_bfloat16 g_qkwh[Bn*Hn*Nn*4096];  // P hi
__device__ __nv_bfloat16 g_qkwl[Bn*Hn*Nn*4096];  // P lo

// bf16 hi/lo split buffers for projection GEMMs
__device__ __nv_bfloat16 g_ahi[NROW*Cn];
__device__ __nv_bfloat16 g_alo[NROW*Cn];
__device__ __nv_bfloat16 g_whi[4*Cn*Cn];
__device__ __nv_bfloat16 g_wlo[4*Cn*Cn];

// ---------------- helpers ----------------
__device__ __forceinline__ uint32_t smem_u32(const void* p) {
    uint32_t a;
    asm("{ .reg .u64 t; cvta.to.shared.u64 t, %1; cvt.u32.u64 %0, t; }"
        : "=r"(a) : "l"(p));
    return a;
}

__device__ __forceinline__ uint32_t pack_bf2(float a, float b) {
    return (uint32_t)__bfloat16_as_ushort(__float2bfloat16_rn(a))
         | ((uint32_t)__bfloat16_as_ushort(__float2bfloat16_rn(b)) << 16);
}

__device__ __forceinline__ void split4(float4 a, uint2& hv, uint2& lv) {
    float h0 = __bfloat162float(__float2bfloat16_rn(a.x));
    float h1 = __bfloat162float(__float2bfloat16_rn(a.y));
    float h2 = __bfloat162float(__float2bfloat16_rn(a.z));
    float h3 = __bfloat162float(__float2bfloat16_rn(a.w));
    hv.x = pack_bf2(a.x, a.y);
    hv.y = pack_bf2(a.z, a.w);
    lv.x = pack_bf2(a.x - h0, a.y - h1);
    lv.y = pack_bf2(a.z - h2, a.w - h3);
}

__device__ __forceinline__ void split1(float v, __nv_bfloat16& h, __nv_bfloat16& l) {
    h = __float2bfloat16_rn(v);
    l = __float2bfloat16_rn(v - __bfloat162float(h));
}

__device__ __forceinline__ void ldm4(uint32_t addr, uint32_t& r0, uint32_t& r1,
                                     uint32_t& r2, uint32_t& r3) {
    asm volatile("ldmatrix.sync.aligned.m8n8.x4.shared.b16 {%0,%1,%2,%3}, [%4];"
                 : "=r"(r0), "=r"(r1), "=r"(r2), "=r"(r3) : "r"(addr));
}

__device__ __forceinline__ void ldm4t(uint32_t addr, uint32_t& r0, uint32_t& r1,
                                      uint32_t& r2, uint32_t& r3) {
    asm volatile("ldmatrix.sync.aligned.m8n8.x4.trans.shared.b16 {%0,%1,%2,%3}, [%4];"
                 : "=r"(r0), "=r"(r1), "=r"(r2), "=r"(r3) : "r"(addr));
}

__device__ __forceinline__ void mma16816(float* d, const uint32_t* a,
                                         uint32_t b0, uint32_t b1) {
    asm volatile("mma.sync.aligned.m16n8k16.row.col.f32.bf16.bf16.f32 "
                 "{%0,%1,%2,%3}, {%4,%5,%6,%7}, {%8,%9}, {%0,%1,%2,%3};"
                 : "+f"(d[0]), "+f"(d[1]), "+f"(d[2]), "+f"(d[3])
                 : "r"(a[0]), "r"(a[1]), "r"(a[2]), "r"(a[3]), "r"(b0), "r"(b1));
}

#define CPA16(dst, src) \
    asm volatile("cp.async.cg.shared.global [%0], [%1], 16;" \
                 :: "r"(dst), "l"(src) : "memory")

// ------------- conversion passes: fp32 -> bf16 hi/lo -------------
__global__ __launch_bounds__(256) void convA_kernel(const float* __restrict__ src)
{
    size_t i = ((size_t)blockIdx.x * 256 + threadIdx.x) * 4;
    float4 v = *(const float4*)(src + i);
    uint2 hv, lv; split4(v, hv, lv);
    *(uint2*)(g_ahi + i) = hv;
    *(uint2*)(g_alo + i) = lv;
}

__global__ __launch_bounds__(256) void convW_kernel(
    const float* __restrict__ wq, const float* __restrict__ wk,
    const float* __restrict__ wv, const float* __restrict__ wo)
{
    const float* src = (blockIdx.y == 0) ? wq : (blockIdx.y == 1) ? wk
                     : (blockIdx.y == 2) ? wv : wo;
    size_t base = (size_t)blockIdx.y * 65536;
    size_t i = ((size_t)blockIdx.x * 256 + threadIdx.x) * 4;
    float4 v = *(const float4*)(src + i);
    uint2 hv, lv; split4(v, hv, lv);
    *(uint2*)(g_whi + base + i) = hv;
    *(uint2*)(g_wlo + base + i) = lv;
}

// ------------- projection GEMM (mma.sync bf16 hi/lo, cp.async, 2 CTAs/SM) -------------
#define GP 40       // smem pitch (bf16 elems)
#define GMAT 10240  // bytes per matrix (128*GP*2)
#define GSTG 40960  // bytes per stage
#define GEMM_SMEM (2*GSTG)

// mode 0: fused q/k/v (blockIdx.z selects); mode 1: output projection (weight idx 3)
__global__ __launch_bounds__(256, 2) void gemm_mma_kernel(
    const float* __restrict__ b0p, const float* __restrict__ b1p,
    const float* __restrict__ b2p, float* __restrict__ dout,
    int mode, float scaleK,
    const float* __restrict__ sinp, const float* __restrict__ cosp)
{
    extern __shared__ char gsm[];
    int z = (mode == 0) ? blockIdx.z : 3;
    float* outp;
    const float* bias;
    float scale = 1.0f;
    bool do_rope = false;
    if (mode == 0) {
        if (z == 0)      { outp = g_q; bias = b0p; do_rope = true; }
        else if (z == 1) { outp = g_k; bias = b1p; do_rope = true; scale = scaleK; }
        else             { outp = g_v; bias = b2p; }
    } else { outp = dout; bias = b0p; }
    const __nv_bfloat16* Whi = g_whi + (size_t)z * 65536;
    const __nv_bfloat16* Wlo = g_wlo + (size_t)z * 65536;

    int tid = threadIdx.x;
    int lane = tid & 31, wid = tid >> 5;
    int warp_m = wid >> 2, warp_n = wid & 3;
    int row0 = blockIdx.x * 128;
    int n0 = blockIdx.y * 128;

    int r0i = tid >> 2, q0 = tid & 3;
    int r1i = (tid + 256) >> 2, q1 = tid & 3;
    uint32_t st0 = (uint32_t)(r0i * GP + q0 * 8) * 2;
    uint32_t st1 = (uint32_t)(r1i * GP + q1 * 8) * 2;
    uint32_t gsb = smem_u32(gsm);

    float acc[4][4][4];
#pragma unroll
    for (int i = 0; i < 4; i++)
#pragma unroll
        for (int j = 0; j < 4; j++)
#pragma unroll
            for (int e = 0; e < 4; e++) acc[i][j][e] = 0.f;

    uint32_t a_off[4], b_off[2];
#pragma unroll
    for (int mi = 0; mi < 4; mi++) {
        int row = warp_m * 64 + mi * 16 + (lane & 15);
        int col = ((lane >> 4) & 1) << 3;
        a_off[mi] = (uint32_t)(row * GP + col) * 2;
    }
#pragma unroll
    for (int p = 0; p < 2; p++) {
        int m = lane >> 3;
        int nrow = warp_n * 32 + p * 16 + ((m >> 1) << 3) + (lane & 7);
        int col = (m & 1) << 3;
        b_off[p] = (uint32_t)(nrow * GP + col) * 2;
    }

    auto issue = [&](int kc) {
        uint32_t sb = gsb + (kc & 1) * GSTG;
        int kn = kc * 32;
        size_t a0 = (size_t)(row0 + r0i) * 256 + kn + q0 * 8;
        size_t a1 = (size_t)(row0 + r1i) * 256 + kn + q1 * 8;
        size_t b0 = (size_t)(n0 + r0i) * 256 + kn + q0 * 8;
        size_t b1 = (size_t)(n0 + r1i) * 256 + kn + q1 * 8;
        CPA16(sb + 0*GMAT + st0, (const void*)(g_ahi + a0));
        CPA16(sb + 0*GMAT + st1, (const void*)(g_ahi + a1));
        CPA16(sb + 1*GMAT + st0, (const void*)(g_alo + a0));
        CPA16(sb + 1*GMAT + st1, (const void*)(g_alo + a1));
        CPA16(sb + 2*GMAT + st0, (const void*)(Whi + b0));
        CPA16(sb + 2*GMAT + st1, (const void*)(Whi + b1));
        CPA16(sb + 3*GMAT + st0, (const void*)(Wlo + b0));
        CPA16(sb + 3*GMAT + st1, (const void*)(Wlo + b1));
        asm volatile("cp.async.commit_group;" ::: "memory");
    };

    issue(0);
    for (int kc = 0; kc < 8; kc++) {
        if (kc < 7) {
            issue(kc + 1);
            asm volatile("cp.async.wait_group 1;" ::: "memory");
        } else {
            asm volatile("cp.async.wait_group 0;" ::: "memory");
        }
        __syncthreads();
        uint32_t sb = gsb + (kc & 1) * GSTG;
#pragma unroll
        for (int ks = 0; ks < 2; ks++) {
            uint32_t kb = (uint32_t)(ks * 16) * 2;
            uint32_t bh[2][4], bl[2][4];
#pragma unroll
            for (int p = 0; p < 2; p++) {
                ldm4(sb + 2*GMAT + b_off[p] + kb, bh[p][0], bh[p][1], bh[p][2], bh[p][3]);
                ldm4(sb + 3*GMAT + b_off[p] + kb, bl[p][0], bl[p][1], bl[p][2], bl[p][3]);
            }
#pragma unroll
            for (int mi = 0; mi < 4; mi++) {
                uint32_t ah[4], al[4];
                ldm4(sb + 0*GMAT + a_off[mi] + kb, ah[0], ah[1], ah[2], ah[3]);
                ldm4(sb + 1*GMAT + a_off[mi] + kb, al[0], al[1], al[2], al[3]);
#pragma unroll
                for (int nj = 0; nj < 4; nj++) {
                    int p = nj >> 1, h = (nj & 1) << 1;
                    mma16816(acc[mi][nj], ah, bh[p][h], bh[p][h + 1]);
                    mma16816(acc[mi][nj], ah, bl[p][h], bl[p][h + 1]);
                    mma16816(acc[mi][nj], al, bh[p][h], bh[p][h + 1]);
                }
            }
        }
        __syncthreads();
    }

#pragma unroll
    for (int mi = 0; mi < 4; mi++) {
        int rbase = row0 + warp_m * 64 + mi * 16 + (lane >> 2);
        int hw0 = rbase & 4095;
        int hw8 = (rbase + 8) & 4095;
#pragma unroll
        for (int nj = 0; nj < 4; nj++) {
            int c = n0 + warp_n * 32 + nj * 8 + ((lane & 3) << 1);
            float b0 = __ldg(bias + c), b1 = __ldg(bias + c + 1);
            float2 o0, o1;
            o0.x = (acc[mi][nj][0] + b0) * scale;
            o0.y = (acc[mi][nj][1] + b1) * scale;
            o1.x = (acc[mi][nj][2] + b0) * scale;
            o1.y = (acc[mi][nj][3] + b1) * scale;
            if (do_rope) {
                int d0 = c & 31;
                float s0 = __ldg(sinp + hw0 * 32 + d0);
                float s1 = __ldg(sinp + hw0 * 32 + d0 + 1);
                float c0v = __ldg(cosp + hw0 * 32 + d0);
                float c1v = __ldg(cosp + hw0 * 32 + d0 + 1);
                float xe = o0.x, xo = o0.y;
                o0.x = xe * c0v - xo * s0;
                o0.y = xo * c1v + xe * s1;
                float s0b = __ldg(sinp + hw8 * 32 + d0);
                float s1b = __ldg(sinp + hw8 * 32 + d0 + 1);
                float c0b = __ldg(cosp + hw8 * 32 + d0);
                float c1b = __ldg(cosp + hw8 * 32 + d0 + 1);
                float xe1 = o1.x, xo1 = o1.y;
                o1.x = xe1 * c0b - xo1 * s0b;
                o1.y = xo1 * c1b + xe1 * s1b;
            }
            *(float2*)(outp + (size_t)rbase * 256 + c) = o0;
            *(float2*)(outp + (size_t)(rbase + 8) * 256 + c) = o1;
        }
    }
}

// ---------------- dt -> da/db ----------------
__device__ __forceinline__ float softplusf(float a) {
    return (a > 20.f) ? a : log1pf(expf(a));
}

__global__ __launch_bounds__(256) void dt_kernel(
    const float* __restrict__ x, const float* __restrict__ dtw,
    const float* __restrict__ dtb, const float* __restrict__ Alog)
{
    int r = blockIdx.x;
    int w = r & 63;
    int h = (r >> 6) & 63;
    int b = r >> 12;
    int c = threadIdx.x;
    int n = c >> 5, d = c & 31;

    float xv = x[r * 256 + c];
    float t0 = xv * dtw[d];
    float t1 = xv * dtw[32 + d];
#pragma unroll
    for (int off = 16; off; off >>= 1) {
        t0 += __shfl_down_sync(0xffffffffu, t0, off);
        t1 += __shfl_down_sync(0xffffffffu, t1, off);
    }
    if (d == 0) {
        float bias = dtb[n];
        float Aa = -expf(Alog[n]);
        float da = softplusf(t0 + bias) * Aa;
        float db = softplusf(t1 + bias) * Aa;
        g_da[((b * 64 + h) * 8 + n) * 64 + w] = da;
        g_db[((b * 64 + w) * 8 + n) * 64 + h] = db;
    }
}

// ---------------- LePE depthwise 5x5 conv (sliding window) ----------------
__global__ __launch_bounds__(256) void lepe_kernel(
    const float* __restrict__ lw, const float* __restrict__ lb)
{
    int blk = blockIdx.x;            // (b*64 + h)*2 + whalf
    int whalf = blk & 1;
    int h = (blk >> 1) & 63;
    int b = blk >> 7;
    int c = threadIdx.x;

    float wt[5][5];
    const float* vrow[5];
    bool rv[5];
#pragma unroll
    for (int ki = 0; ki < 5; ki++) {
        int hh = h + ki - 2;
        rv[ki] = ((unsigned)hh < 64u);
        vrow[ki] = g_v + ((size_t)((b * 64 + (rv[ki] ? hh : 0)) * 64)) * 256 + c;
#pragma unroll
        for (int kj = 0; kj < 5; kj++)
            wt[ki][kj] = __ldg(lw + (ki * 5 + kj) * 256 + c);
    }
    float lbv = __ldg(lb + c);

    float win[5][5];
    int w0 = whalf * 32;
#pragma unroll
    for (int dj = 0; dj < 4; dj++) {
        int col = w0 - 2 + dj;
        bool cv = ((unsigned)col < 64u);
#pragma unroll
        for (int ki = 0; ki < 5; ki++)
            win[ki][dj] = (rv[ki] && cv) ? __ldg(vrow[ki] + col * 256) : 0.f;
    }

    float* outb = g_lepe + ((size_t)((b * 64 + h) * 64)) * 256 + c;
    for (int w = w0; w < w0 + 32; w++) {
        int col = w + 2;
        bool cv = (col < 64);
#pragma unroll
        for (int ki = 0; ki < 5; ki++)
            win[ki][4] = (rv[ki] && cv) ? __ldg(vrow[ki] + col * 256) : 0.f;
        float acc = lbv;
#pragma unroll
        for (int ki = 0; ki < 5; ki++)
#pragma unroll
            for (int kj = 0; kj < 5; kj++)
                acc += win[ki][kj] * wt[ki][kj];
        outb[w * 256] = acc;
#pragma unroll
        for (int ki = 0; ki < 5; ki++)
#pragma unroll
            for (int dj = 0; dj < 4; dj++)
                win[ki][dj] = win[ki][dj + 1];
    }
}

// ---------------- attention (mma.sync bf16 hi/lo; trans-ldmatrix B) ----------------
#define AT_QHI 0
#define AT_QLO 5120
#define AT_KHI 10240
#define AT_KLO 15360
#define AT_VHI 20480
#define AT_VLO 25600
#define AT_WHI 30720
#define AT_WLO 35840
#define AT_PHI 0
#define AT_PLO 9216
#define AT_SW  30720
#define AT_CSW 47616
#define ATTN_SMEM_W 47872
#define AT_SH  40960
#define AT_CSH 57856
#define ATTN_SMEM_H 58112

__device__ __forceinline__ void s_phase(uint32_t sbase, int lane, int wid,
                                        float* S, const float* cs)
{
    int wm = wid >> 2, wn = wid & 3;
    uint32_t a_off[2];
#pragma unroll
    for (int mi = 0; mi < 2; mi++) {
        int row = wm * 32 + mi * 16 + (lane & 15);
        int col = ((lane >> 4) & 1) << 3;
        a_off[mi] = (uint32_t)(row * GP + col) * 2;
    }
    int m = lane >> 3;
    uint32_t b_off = (uint32_t)((wn * 16 + ((m >> 1) << 3) + (lane & 7)) * GP + ((m & 1) << 3)) * 2;

    float sacc[2][2][4];
#pragma unroll
    for (int a = 0; a < 2; a++)
#pragma unroll
        for (int b2 = 0; b2 < 2; b2++)
#pragma unroll
            for (int e = 0; e < 4; e++) sacc[a][b2][e] = 0.f;

#pragma unroll
    for (int ks = 0; ks < 2; ks++) {
        uint32_t kb = (uint32_t)(ks * 16) * 2;
        uint32_t ah[2][4], al[2][4], bh[4], bl[4];
#pragma unroll
        for (int mi = 0; mi < 2; mi++) {
            ldm4(sbase + AT_QHI + a_off[mi] + kb, ah[mi][0], ah[mi][1], ah[mi][2], ah[mi][3]);
            ldm4(sbase + AT_QLO + a_off[mi] + kb, al[mi][0], al[mi][1], al[mi][2], al[mi][3]);
        }
        ldm4(sbase + AT_KHI + b_off + kb, bh[0], bh[1], bh[2], bh[3]);
        ldm4(sbase + AT_KLO + b_off + kb, bl[0], bl[1], bl[2], bl[3]);
#pragma unroll
        for (int mi = 0; mi < 2; mi++) {
#pragma unroll
            for (int nj = 0; nj < 2; nj++) {
                int h2 = nj * 2;
                mma16816(sacc[mi][nj], ah[mi], bh[h2], bh[h2 + 1]);
                mma16816(sacc[mi][nj], ah[mi], bl[h2], bl[h2 + 1]);
                mma16816(sacc[mi][nj], al[mi], bh[h2], bh[h2 + 1]);
            }
        }
    }
#pragma unroll
    for (int mi = 0; mi < 2; mi++) {
#pragma unroll
        for (int nj = 0; nj < 2; nj++) {
            int r0 = wm * 32 + mi * 16 + (lane >> 2);
            int c0 = wn * 16 + nj * 8 + ((lane & 3) << 1);
            float cr0 = cs[r0], cr8 = cs[r0 + 8];
            float cc0 = cs[c0], cc1 = cs[c0 + 1];
            S[r0 * 66 + c0]       = sacc[mi][nj][0] + ((r0 >= c0)     ? cr0 - cc0 : cc0 - cr0);
            S[r0 * 66 + c0 + 1]   = sacc[mi][nj][1] + ((r0 >= c0 + 1) ? cr0 - cc1 : cc1 - cr0);
            S[(r0 + 8) * 66 + c0]     = sacc[mi][nj][2] + ((r0 + 8 >= c0)     ? cr8 - cc0 : cc0 - cr8);
            S[(r0 + 8) * 66 + c0 + 1] = sacc[mi][nj][3] + ((r0 + 8 >= c0 + 1) ? cr8 - cc1 : cc1 - cr8);
        }
    }
}

__device__ __forceinline__ void softmax_phase(char* sm, int lane, int wid, float* S)
{
#pragma unroll
    for (int rr = 0; rr < 8; rr++) {
        int i = wid * 8 + rr;
        float v0 = S[i * 66 + lane], v1 = S[i * 66 + lane + 32];
        float mx = fmaxf(v0, v1);
#pragma unroll
        for (int off = 16; off; off >>= 1) mx = fmaxf(mx, __shfl_xor_sync(0xffffffffu, mx, off));
        float e0 = __expf(v0 - mx), e1 = __expf(v1 - mx);
        float s = e0 + e1;
#pragma unroll
        for (int off = 16; off; off >>= 1) s += __shfl_xor_sync(0xffffffffu, s, off);
        float inv = 1.f / s;
        float p0 = e0 * inv, p1 = e1 * inv;
        __nv_bfloat16 h0, l0, h1, l1;
        split1(p0, h0, l0);
        split1(p1, h1, l1);
        *(__nv_bfloat16*)(sm + AT_PHI + (i * 72 + lane) * 2) = h0;
        *(__nv_bfloat16*)(sm + AT_PHI + (i * 72 + lane + 32) * 2) = h1;
        *(__nv_bfloat16*)(sm + AT_PLO + (i * 72 + lane) * 2) = l0;
        *(__nv_bfloat16*)(sm + AT_PLO + (i * 72 + lane + 32) * 2) = l1;
    }
}

__device__ __forceinline__ void pv_phase(uint32_t sbase, int lane, int wid,
                                         uint32_t bhi, uint32_t blo, float facc[2][4])
{
    int wm = wid >> 1, wn = wid & 1;
    uint32_t a_off = (uint32_t)((wm * 16 + (lane & 15)) * 72 + (((lane >> 4) & 1) << 3)) * 2;
    int g = lane >> 3, j8 = lane & 7;
    uint32_t b_off = (uint32_t)(((g & 1) * 8 + j8) * GP + wn * 16 + ((g >> 1) << 3)) * 2;
#pragma unroll
    for (int ks = 0; ks < 4; ks++) {
        uint32_t kbA = (uint32_t)(ks * 16) * 2;
        uint32_t kbB = (uint32_t)(ks * 16 * GP) * 2;
        uint32_t ah[4], al[4], bh[4], bl[4];
        ldm4(sbase + AT_PHI + a_off + kbA, ah[0], ah[1], ah[2], ah[3]);
        ldm4(sbase + AT_PLO + a_off + kbA, al[0], al[1], al[2], al[3]);
        ldm4t(bhi + b_off + kbB, bh[0], bh[1], bh[2], bh[3]);
        ldm4t(blo + b_off + kbB, bl[0], bl[1], bl[2], bl[3]);
#pragma unroll
        for (int nj = 0; nj < 2; nj++) {
            int h2 = nj * 2;
            mma16816(facc[nj], ah, bh[h2], bh[h2 + 1]);
            mma16816(facc[nj], ah, bl[h2], bl[h2 + 1]);
            mma16816(facc[nj], al, bh[h2], bh[h2 + 1]);
        }
    }
}

__global__ __launch_bounds__(256) void attn_w_kernel(void)
{
    extern __shared__ char sm[];
    int blk = blockIdx.x;
    int n = blk & 7;
    int h = (blk >> 3) & 63;
    int b = blk >> 9;
    int tid = threadIdx.x, lane = tid & 31, wid = tid >> 5;
    int qbase = ((b * 64 + h) * 64) * 256 + n * 32;
    float* S = (float*)(sm + AT_SW);
    float* cs = (float*)(sm + AT_CSW);
    uint32_t sbase = smem_u32(sm);

    for (int e = tid; e < 512; e += 256) {
        int i = e >> 3, d4 = (e & 7) << 2;
        float4 qv = *(const float4*)(g_q + qbase + i * 256 + d4);
        float4 kv = *(const float4*)(g_k + qbase + i * 256 + d4);
        float4 vv = *(const float4*)(g_v + qbase + i * 256 + d4);
        uint2 hv, lv;
        uint32_t so = (uint32_t)(i * GP + d4) * 2;
        split4(qv, hv, lv);
        *(uint2*)(sm + AT_QHI + so) = hv; *(uint2*)(sm + AT_QLO + so) = lv;
        split4(kv, hv, lv);
        *(uint2*)(sm + AT_KHI + so) = hv; *(uint2*)(sm + AT_KLO + so) = lv;
        split4(vv, hv, lv);
        *(uint2*)(sm + AT_VHI + so) = hv; *(uint2*)(sm + AT_VLO + so) = lv;
    }
    if (tid == 0) {
        float run = 0.f;
        const float* dap = g_da + blk * 64;
        for (int j = 0; j < 64; j++) { run += dap[j]; cs[j] = run; }
    }
    __syncthreads();

    s_phase(sbase, lane, wid, S, cs);
    __syncthreads();

    softmax_phase(sm, lane, wid, S);
    __syncthreads();

    __nv_bfloat16* gh = g_qkwh + (size_t)blk * 4096;
    __nv_bfloat16* gl = g_qkwl + (size_t)blk * 4096;
    for (int e = tid; e < 512; e += 256) {
        int row = e >> 3, c8 = (e & 7) << 3;
        *(uint4*)(gh + row * 64 + c8) = *(uint4*)(sm + AT_PHI + (row * 72 + c8) * 2);
        *(uint4*)(gl + row * 64 + c8) = *(uint4*)(sm + AT_PLO + (row * 72 + c8) * 2);
    }

    float facc[2][4];
#pragma unroll
    for (int nj = 0; nj < 2; nj++)
#pragma unroll
        for (int e = 0; e < 4; e++) facc[nj][e] = 0.f;
    pv_phase(sbase, lane, wid, sbase + AT_VHI, sbase + AT_VLO, facc);

    float* vwp = g_vw + (size_t)blk * 2048;
    int wm = wid >> 1, wn = wid & 1;
#pragma unroll
    for (int nj = 0; nj < 2; nj++) {
        int r0 = wm * 16 + (lane >> 2);
        int d0 = wn * 16 + nj * 8 + ((lane & 3) << 1);
        float2 o0 = {facc[nj][0], facc[nj][1]};
        float2 o1 = {facc[nj][2], facc[nj][3]};
        *(float2*)(vwp + r0 * 32 + d0) = o0;
        *(float2*)(vwp + (r0 + 8) * 32 + d0) = o1;
    }
}

__global__ __launch_bounds__(256) void attn_h_kernel(void)
{
    extern __shared__ char sm[];
    int blk = blockIdx.x;
    int n = blk & 7;
    int x = (blk >> 3) & 63;
    int b = blk >> 9;
    int tid = threadIdx.x, lane = tid & 31, wid = tid >> 5;
    int qbase = (b * 64 * 64 + x) * 256 + n * 32;
    float* S = (float*)(sm + AT_SH);
    float* cs = (float*)(sm + AT_CSH);
    uint32_t sbase = smem_u32(sm);

    for (int e = tid; e < 512; e += 256) {
        int i = e >> 3, d4 = (e & 7) << 2;
        float4 qv = *(const float4*)(g_q + qbase + i * 16384 + d4);
        float4 kv = *(const float4*)(g_k + qbase + i * 16384 + d4);
        float4 vv = *(const float4*)(g_v + qbase + i * 16384 + d4);
        float4 wv = *(const float4*)(g_vw + ((size_t)((b * 64 + i) * 8 + n)) * 2048 + x * 32 + d4);
        uint2 hv, lv;
        uint32_t so = (uint32_t)(i * GP + d4) * 2;
        split4(qv, hv, lv);
        *(uint2*)(sm + AT_QHI + so) = hv; *(uint2*)(sm + AT_QLO + so) = lv;
        split4(kv, hv, lv);
        *(uint2*)(sm + AT_KHI + so) = hv; *(uint2*)(sm + AT_KLO + so) = lv;
        split4(vv, hv, lv);
        *(uint2*)(sm + AT_VHI + so) = hv; *(uint2*)(sm + AT_VLO + so) = lv;
        split4(wv, hv, lv);
        *(uint2*)(sm + AT_WHI + so) = hv; *(uint2*)(sm + AT_WLO + so) = lv;
    }
    if (tid == 0) {
        float run = 0.f;
        const float* dbp = g_db + blk * 64;
        for (int j = 0; j < 64; j++) { run += dbp[j]; cs[j] = run; }
    }
    __syncthreads();

    s_phase(sbase, lane, wid, S, cs);
    __syncthreads();

    softmax_phase(sm, lane, wid, S);
    __syncthreads();

    float facc1[2][4], facc2[2][4];
#pragma unroll
    for (int nj = 0; nj < 2; nj++)
#pragma unroll
        for (int e = 0; e < 4; e++) { facc1[nj][e] = 0.f; facc2[nj][e] = 0.f; }
    pv_phase(sbase, lane, wid, sbase + AT_VHI, sbase + AT_VLO, facc1);
    pv_phase(sbase, lane, wid, sbase + AT_WHI, sbase + AT_WLO, facc2);

    float* v2p = g_vh2 + (size_t)blk * 2048;
    int wm = wid >> 1, wn = wid & 1;
#pragma unroll
    for (int nj = 0; nj < 2; nj++) {
        int r0 = wm * 16 + (lane >> 2);
        int d0 = wn * 16 + nj * 8 + ((lane & 3) << 1);
        float2 o0 = {facc1[nj][0], facc1[nj][1]};
        float2 o1 = {facc1[nj][2], facc1[nj][3]};
        *(float2*)(v2p + r0 * 32 + d0) = o0;
        *(float2*)(v2p + (r0 + 8) * 32 + d0) = o1;
        float2 p0 = {0.5f * facc2[nj][0], 0.5f * facc2[nj][1]};
        float2 p1 = {0.5f * facc2[nj][2], 0.5f * facc2[nj][3]};
        *(float2*)(g_pre + (size_t)((b * 64 + r0) * 64 + x) * 256 + n * 32 + d0) = p0;
        *(float2*)(g_pre + (size_t)((b * 64 + r0 + 8) * 64 + x) * 256 + n * 32 + d0) = p1;
    }
}

// out2: final = pre + 0.5*(qk_w @ v_h2) + lepe -> bf16 hi/lo split (for final GEMM)
#define O2_PHI 0
#define O2_PLO 9216
#define O2_VHI 18432
#define O2_VLO 23552
#define OUT2_SMEM 28672

__global__ __launch_bounds__(256) void out2_kernel(void)
{
    extern __shared__ char sm[];
    int blk = blockIdx.x;
    int n = blk & 7;
    int y = (blk >> 3) & 63;
    int b = blk >> 9;
    int tid = threadIdx.x, lane = tid & 31, wid = tid >> 5;
    uint32_t sbase = smem_u32(sm);

    const __nv_bfloat16* gh = g_qkwh + (size_t)blk * 4096;
    const __nv_bfloat16* gl = g_qkwl + (size_t)blk * 4096;
    for (int e = tid; e < 512; e += 256) {
        int row = e >> 3, c8 = (e & 7) << 3;
        *(uint4*)(sm + O2_PHI + (row * 72 + c8) * 2) = *(const uint4*)(gh + row * 64 + c8);
        *(uint4*)(sm + O2_PLO + (row * 72 + c8) * 2) = *(const uint4*)(gl + row * 64 + c8);
    }
    for (int e = tid; e < 512; e += 256) {
        int j = e >> 3, d4 = (e & 7) << 2;
        float4 vv = *(const float4*)(g_vh2 + ((size_t)((b * 64 + j) * 8 + n)) * 2048 + y * 32 + d4);
        uint2 hv, lv;
        split4(vv, hv, lv);
        uint32_t so = (uint32_t)(j * GP + d4) * 2;
        *(uint2*)(sm + O2_VHI + so) = hv;
        *(uint2*)(sm + O2_VLO + so) = lv;
    }
    __syncthreads();

    int wm = wid >> 1, wn = wid & 1;
    uint32_t a_off = (uint32_t)((wm * 16 + (lane & 15)) * 72 + (((lane >> 4) & 1) << 3)) * 2;
    int g = lane >> 3, j8 = lane & 7;
    uint32_t b_off = (uint32_t)(((g & 1) * 8 + j8) * GP + wn * 16 + ((g >> 1) << 3)) * 2;
    float facc[2][4];
#pragma unroll
    for (int nj = 0; nj < 2; nj++)
#pragma unroll
        for (int e = 0; e < 4; e++) facc[nj][e] = 0.f;
#pragma unroll
    for (int ks = 0; ks < 4; ks++) {
        uint32_t kbA = (uint32_t)(ks * 16) * 2;
        uint32_t kbB = (uint32_t)(ks * 16 * GP) * 2;
        uint32_t ah[4], al[4], bh[4], bl[4];
        ldm4(sbase + O2_PHI + a_off + kbA, ah[0], ah[1], ah[2], ah[3]);
        ldm4(sbase + O2_PLO + a_off + kbA, al[0], al[1], al[2], al[3]);
        ldm4t(sbase + O2_VHI + b_off + kbB, bh[0], bh[1], bh[2], bh[3]);
        ldm4t(sbase + O2_VLO + b_off + kbB, bl[0], bl[1], bl[2], bl[3]);
#pragma unroll
        for (int nj = 0; nj < 2; nj++) {
            int h2 = nj * 2;
            mma16816(facc[nj], ah, bh[h2], bh[h2 + 1]);
            mma16816(facc[nj], ah, bl[h2], bl[h2 + 1]);
            mma16816(facc[nj], al, bh[h2], bh[h2 + 1]);
        }
    }

#pragma unroll
    for (int nj = 0; nj < 2; nj++) {
        int r0 = wm * 16 + (lane >> 2);
        int d0 = wn * 16 + nj * 8 + ((lane & 3) << 1);
        size_t a0 = (size_t)((b * 64 + y) * 64 + r0) * 256 + n * 32 + d0;
        size_t a1 = (size_t)((b * 64 + y) * 64 + r0 + 8) * 256 + n * 32 + d0;
        float2 pr0 = *(float2*)(g_pre + a0);
        float2 le0 = *(float2*)(g_lepe + a0);
        float2 pr1 = *(float2*)(g_pre + a1);
        float2 le1 = *(float2*)(g_lepe + a1);
        float fx0 = pr0.x + 0.5f * facc[nj][0] + le0.x;
        float fy0 = pr0.y + 0.5f * facc[nj][1] + le0.y;
        float fx1 = pr1.x + 0.5f * facc[nj][2] + le1.x;
        float fy1 = pr1.y + 0.5f * facc[nj][3] + le1.y;
        // split directly into projection-GEMM input buffers
        __nv_bfloat16 hx0, lx0, hy0, ly0, hx1, lx1, hy1, ly1;
        split1(fx0, hx0, lx0); split1(fy0, hy0, ly0);
        split1(fx1, hx1, lx1); split1(fy1, hy1, ly1);
        *(uint32_t*)(g_ahi + a0) = (uint32_t)__bfloat16_as_ushort(hx0)
                                 | ((uint32_t)__bfloat16_as_ushort(hy0) << 16);
        *(uint32_t*)(g_alo + a0) = (uint32_t)__bfloat16_as_ushort(lx0)
                                 | ((uint32_t)__bfloat16_as_ushort(ly0) << 16);
        *(uint32_t*)(g_ahi + a1) = (uint32_t)__bfloat16_as_ushort(hx1)
                                 | ((uint32_t)__bfloat16_as_ushort(hy1) << 16);
        *(uint32_t*)(g_alo + a1) = (uint32_t)__bfloat16_as_ushort(lx1)
                                 | ((uint32_t)__bfloat16_as_ushort(ly1) << 16);
    }
}

// ---------------- launch ----------------
extern "C" void kernel_launch(void* const* d_in, const int* in_sizes, int n_in,
                              void* d_out, int out_size)
{
    const float* x    = (const float*)d_in[0];
    const float* sinp = (const float*)d_in[1];
    const float* cosp = (const float*)d_in[2];
    const float* Wq   = (const float*)d_in[3];
    const float* bq   = (const float*)d_in[4];
    const float* Wk   = (const float*)d_in[5];
    const float* bk   = (const float*)d_in[6];
    const float* Wv   = (const float*)d_in[7];
    const float* bv   = (const float*)d_in[8];
    const float* Wo   = (const float*)d_in[9];
    const float* bo   = (const float*)d_in[10];
    const float* lw   = (const float*)d_in[11];
    const float* lb   = (const float*)d_in[12];
    const float* dtw  = (const float*)d_in[13];
    const float* dtb  = (const float*)d_in[14];
    const float* Alog = (const float*)d_in[15];
    float* out = (float*)d_out;

    const float scaling = 0.17677669529663687f;   // 32^-0.5

    cudaFuncSetAttribute(gemm_mma_kernel,
                         cudaFuncAttributeMaxDynamicSharedMemorySize, GEMM_SMEM);
    cudaFuncSetAttribute(attn_w_kernel,
                         cudaFuncAttributeMaxDynamicSharedMemorySize, ATTN_SMEM_W);
    cudaFuncSetAttribute(attn_h_kernel,
                         cudaFuncAttributeMaxDynamicSharedMemorySize, ATTN_SMEM_H);
    cudaFuncSetAttribute(out2_kernel,
                         cudaFuncAttributeMaxDynamicSharedMemorySize, OUT2_SMEM);

    int convA_blocks = (NROW * Cn) / (256 * 4);   // 16384

    convA_kernel<<<convA_blocks, 256>>>(x);                           // 0
    convW_kernel<<<dim3(64, 4), 256>>>(Wq, Wk, Wv, Wo);               // 1
    dt_kernel<<<NROW, 256>>>(x, dtw, dtb, Alog);                      // 2

    gemm_mma_kernel<<<dim3(NROW / 128, 2, 3), 256, GEMM_SMEM>>>(
        bq, bk, bv, nullptr, 0, scaling, sinp, cosp);                 // 3 (fused q/k/v)

    lepe_kernel<<<Bn * Hn * 2, 256>>>(lw, lb);                        // 4

    attn_w_kernel<<<Bn * Hn * Nn, 256, ATTN_SMEM_W>>>();              // 5 <- profiled
    attn_h_kernel<<<Bn * Wn * Nn, 256, ATTN_SMEM_H>>>();              // 6
    out2_kernel<<<Bn * Hn * Nn, 256, OUT2_SMEM>>>();                  // 7

    gemm_mma_kernel<<<dim3(NROW / 128, 2, 1), 256, GEMM_SMEM>>>(
        bo, nullptr, nullptr, out, 1, 1.0f, sinp, cosp);              // 8 (output proj)
}

// round 10
// speedup vs baseline: 1.5953x; 1.0761x over previous
#include <cuda_runtime.h>
#include <cuda_bf16.h>
#include <math.h>
#include <stdint.h>

#define Bn 16
#define Hn 64
#define Wn 64
#define Cn 256
#define Nn 8
#define Dn 32
#define NROW (Bn*Hn*Wn)   // 65536

// ---------------- scratch (device globals; no allocation) ----------------
__device__ float g_q[NROW*Cn];
__device__ float g_k[NROW*Cn];
__device__ float g_v[NROW*Cn];
__device__ float g_lepe[NROW*Cn];
__device__ float g_pre[NROW*Cn];
__device__ float g_vw[Bn*Hn*Nn*64*32];       // [b][h][n][w][d]
__device__ float g_vh2[Bn*Wn*Nn*64*32];      // [b][w][n][h][d]
__device__ float g_da[Bn*Hn*Nn*Wn];          // [b][h][n][w]
__device__ float g_db[Bn*Wn*Nn*Hn];          // [b][w][n][h]
__device__ __nv_bfloat16 g_qkwh[Bn*Hn*Nn*4096];  // P hi
__device__ __nv_bfloat16 g_qkwl[Bn*Hn*Nn*4096];  // P lo

// bf16 hi/lo split buffers for projection GEMMs
__device__ __nv_bfloat16 g_ahi[NROW*Cn];
__device__ __nv_bfloat16 g_alo[NROW*Cn];
__device__ __nv_bfloat16 g_whi[4*Cn*Cn];
__device__ __nv_bfloat16 g_wlo[4*Cn*Cn];

// ---------------- helpers ----------------
__device__ __forceinline__ uint32_t smem_u32(const void* p) {
    uint32_t a;
    asm("{ .reg .u64 t; cvta.to.shared.u64 t, %1; cvt.u32.u64 %0, t; }"
        : "=r"(a) : "l"(p));
    return a;
}

__device__ __forceinline__ uint32_t pack_bf2(float a, float b) {
    return (uint32_t)__bfloat16_as_ushort(__float2bfloat16_rn(a))
         | ((uint32_t)__bfloat16_as_ushort(__float2bfloat16_rn(b)) << 16);
}

__device__ __forceinline__ void split4(float4 a, uint2& hv, uint2& lv) {
    float h0 = __bfloat162float(__float2bfloat16_rn(a.x));
    float h1 = __bfloat162float(__float2bfloat16_rn(a.y));
    float h2 = __bfloat162float(__float2bfloat16_rn(a.z));
    float h3 = __bfloat162float(__float2bfloat16_rn(a.w));
    hv.x = pack_bf2(a.x, a.y);
    hv.y = pack_bf2(a.z, a.w);
    lv.x = pack_bf2(a.x - h0, a.y - h1);
    lv.y = pack_bf2(a.z - h2, a.w - h3);
}

__device__ __forceinline__ void split1(float v, __nv_bfloat16& h, __nv_bfloat16& l) {
    h = __float2bfloat16_rn(v);
    l = __float2bfloat16_rn(v - __bfloat162float(h));
}

__device__ __forceinline__ void ldm4(uint32_t addr, uint32_t& r0, uint32_t& r1,
                                     uint32_t& r2, uint32_t& r3) {
    asm volatile("ldmatrix.sync.aligned.m8n8.x4.shared.b16 {%0,%1,%2,%3}, [%4];"
                 : "=r"(r0), "=r"(r1), "=r"(r2), "=r"(r3) : "r"(addr));
}

__device__ __forceinline__ void ldm4t(uint32_t addr, uint32_t& r0, uint32_t& r1,
                                      uint32_t& r2, uint32_t& r3) {
    asm volatile("ldmatrix.sync.aligned.m8n8.x4.trans.shared.b16 {%0,%1,%2,%3}, [%4];"
                 : "=r"(r0), "=r"(r1), "=r"(r2), "=r"(r3) : "r"(addr));
}

__device__ __forceinline__ void mma16816(float* d, const uint32_t* a,
                                         uint32_t b0, uint32_t b1) {
    asm volatile("mma.sync.aligned.m16n8k16.row.col.f32.bf16.bf16.f32 "
                 "{%0,%1,%2,%3}, {%4,%5,%6,%7}, {%8,%9}, {%0,%1,%2,%3};"
                 : "+f"(d[0]), "+f"(d[1]), "+f"(d[2]), "+f"(d[3])
                 : "r"(a[0]), "r"(a[1]), "r"(a[2]), "r"(a[3]), "r"(b0), "r"(b1));
}

#define CPA16(dst, src) \
    asm volatile("cp.async.cg.shared.global [%0], [%1], 16;" \
                 :: "r"(dst), "l"(src) : "memory")

// ------------- fused: x -> bf16 hi/lo split  +  dt -> da/db -------------
__device__ __forceinline__ float softplusf(float a) {
    return (a > 20.f) ? a : log1pf(expf(a));
}

__global__ __launch_bounds__(256) void dtconv_kernel(
    const float* __restrict__ x, const float* __restrict__ dtw,
    const float* __restrict__ dtb, const float* __restrict__ Alog)
{
    int tid = threadIdx.x;
    int row_local = tid >> 6;                 // 4 rows per block
    int lane = tid & 31;
    int t64 = tid & 63;
    int c4 = t64 << 2;
    int r = blockIdx.x * 4 + row_local;
    size_t idx = (size_t)r * 256 + c4;

    float4 v = *(const float4*)(x + idx);
    uint2 hv, lv; split4(v, hv, lv);
    *(uint2*)(g_ahi + idx) = hv;
    *(uint2*)(g_alo + idx) = lv;

    int d4 = c4 & 31;
    float t0 = v.x * dtw[d4] + v.y * dtw[d4 + 1] + v.z * dtw[d4 + 2] + v.w * dtw[d4 + 3];
    float t1 = v.x * dtw[32 + d4] + v.y * dtw[32 + d4 + 1]
             + v.z * dtw[32 + d4 + 2] + v.w * dtw[32 + d4 + 3];
#pragma unroll
    for (int off = 4; off; off >>= 1) {
        t0 += __shfl_down_sync(0xffffffffu, t0, off);
        t1 += __shfl_down_sync(0xffffffffu, t1, off);
    }
    if ((lane & 7) == 0) {
        int n = t64 >> 3;
        int w = r & 63, h = (r >> 6) & 63, b = r >> 12;
        float bias = dtb[n];
        float Aa = -expf(Alog[n]);
        float da = softplusf(t0 + bias) * Aa;
        float db = softplusf(t1 + bias) * Aa;
        g_da[((b * 64 + h) * 8 + n) * 64 + w] = da;
        g_db[((b * 64 + w) * 8 + n) * 64 + h] = db;
    }
}

__global__ __launch_bounds__(256) void convW_kernel(
    const float* __restrict__ wq, const float* __restrict__ wk,
    const float* __restrict__ wv, const float* __restrict__ wo)
{
    const float* src = (blockIdx.y == 0) ? wq : (blockIdx.y == 1) ? wk
                     : (blockIdx.y == 2) ? wv : wo;
    size_t base = (size_t)blockIdx.y * 65536;
    size_t i = ((size_t)blockIdx.x * 256 + threadIdx.x) * 4;
    float4 v = *(const float4*)(src + i);
    uint2 hv, lv; split4(v, hv, lv);
    *(uint2*)(g_whi + base + i) = hv;
    *(uint2*)(g_wlo + base + i) = lv;
}

// ------------- projection GEMM (mma.sync bf16 hi/lo, cp.async, 2 CTAs/SM) -------------
// Grid: mode 0: (6, 512): x = z*2 + col  (consecutive bids share A block -> L2 reuse)
//       mode 1: (2, 512): x = col, z = 3
#define GP 40       // smem pitch (bf16 elems)
#define GMAT 10240  // bytes per matrix (128*GP*2)
#define GSTG 40960  // bytes per stage
#define GEMM_SMEM (2*GSTG)

__global__ __launch_bounds__(256, 2) void gemm_mma_kernel(
    const float* __restrict__ b0p, const float* __restrict__ b1p,
    const float* __restrict__ b2p, float* __restrict__ dout,
    int mode, float scaleK,
    const float* __restrict__ sinp, const float* __restrict__ cosp)
{
    extern __shared__ char gsm[];
    int z, col;
    if (mode == 0) { z = blockIdx.x >> 1; col = blockIdx.x & 1; }
    else           { z = 3;               col = blockIdx.x; }
    float* outp;
    const float* bias;
    float scale = 1.0f;
    bool do_rope = false;
    if (mode == 0) {
        if (z == 0)      { outp = g_q; bias = b0p; do_rope = true; }
        else if (z == 1) { outp = g_k; bias = b1p; do_rope = true; scale = scaleK; }
        else             { outp = g_v; bias = b2p; }
    } else { outp = dout; bias = b0p; }
    const __nv_bfloat16* Whi = g_whi + (size_t)z * 65536;
    const __nv_bfloat16* Wlo = g_wlo + (size_t)z * 65536;

    int tid = threadIdx.x;
    int lane = tid & 31, wid = tid >> 5;
    int warp_m = wid >> 2, warp_n = wid & 3;
    int row0 = blockIdx.y * 128;
    int n0 = col * 128;

    int r0i = tid >> 2, q0 = tid & 3;
    int r1i = (tid + 256) >> 2, q1 = tid & 3;
    uint32_t st0 = (uint32_t)(r0i * GP + q0 * 8) * 2;
    uint32_t st1 = (uint32_t)(r1i * GP + q1 * 8) * 2;
    uint32_t gsb = smem_u32(gsm);

    float acc[4][4][4];
#pragma unroll
    for (int i = 0; i < 4; i++)
#pragma unroll
        for (int j = 0; j < 4; j++)
#pragma unroll
            for (int e = 0; e < 4; e++) acc[i][j][e] = 0.f;

    uint32_t a_off[4], b_off[2];
#pragma unroll
    for (int mi = 0; mi < 4; mi++) {
        int row = warp_m * 64 + mi * 16 + (lane & 15);
        int colb = ((lane >> 4) & 1) << 3;
        a_off[mi] = (uint32_t)(row * GP + colb) * 2;
    }
#pragma unroll
    for (int p = 0; p < 2; p++) {
        int m = lane >> 3;
        int nrow = warp_n * 32 + p * 16 + ((m >> 1) << 3) + (lane & 7);
        int colb = (m & 1) << 3;
        b_off[p] = (uint32_t)(nrow * GP + colb) * 2;
    }

    auto issue = [&](int kc) {
        uint32_t sb = gsb + (kc & 1) * GSTG;
        int kn = kc * 32;
        size_t a0 = (size_t)(row0 + r0i) * 256 + kn + q0 * 8;
        size_t a1 = (size_t)(row0 + r1i) * 256 + kn + q1 * 8;
        size_t b0 = (size_t)(n0 + r0i) * 256 + kn + q0 * 8;
        size_t b1 = (size_t)(n0 + r1i) * 256 + kn + q1 * 8;
        CPA16(sb + 0*GMAT + st0, (const void*)(g_ahi + a0));
        CPA16(sb + 0*GMAT + st1, (const void*)(g_ahi + a1));
        CPA16(sb + 1*GMAT + st0, (const void*)(g_alo + a0));
        CPA16(sb + 1*GMAT + st1, (const void*)(g_alo + a1));
        CPA16(sb + 2*GMAT + st0, (const void*)(Whi + b0));
        CPA16(sb + 2*GMAT + st1, (const void*)(Whi + b1));
        CPA16(sb + 3*GMAT + st0, (const void*)(Wlo + b0));
        CPA16(sb + 3*GMAT + st1, (const void*)(Wlo + b1));
        asm volatile("cp.async.commit_group;" ::: "memory");
    };

    issue(0);
    for (int kc = 0; kc < 8; kc++) {
        if (kc < 7) {
            issue(kc + 1);
            asm volatile("cp.async.wait_group 1;" ::: "memory");
        } else {
            asm volatile("cp.async.wait_group 0;" ::: "memory");
        }
        __syncthreads();
        uint32_t sb = gsb + (kc & 1) * GSTG;
#pragma unroll
        for (int ks = 0; ks < 2; ks++) {
            uint32_t kb = (uint32_t)(ks * 16) * 2;
            uint32_t bh[2][4], bl[2][4];
#pragma unroll
            for (int p = 0; p < 2; p++) {
                ldm4(sb + 2*GMAT + b_off[p] + kb, bh[p][0], bh[p][1], bh[p][2], bh[p][3]);
                ldm4(sb + 3*GMAT + b_off[p] + kb, bl[p][0], bl[p][1], bl[p][2], bl[p][3]);
            }
#pragma unroll
            for (int mi = 0; mi < 4; mi++) {
                uint32_t ah[4], al[4];
                ldm4(sb + 0*GMAT + a_off[mi] + kb, ah[0], ah[1], ah[2], ah[3]);
                ldm4(sb + 1*GMAT + a_off[mi] + kb, al[0], al[1], al[2], al[3]);
#pragma unroll
                for (int nj = 0; nj < 4; nj++) {
                    int p = nj >> 1, h = (nj & 1) << 1;
                    mma16816(acc[mi][nj], ah, bh[p][h], bh[p][h + 1]);
                    mma16816(acc[mi][nj], ah, bl[p][h], bl[p][h + 1]);
                    mma16816(acc[mi][nj], al, bh[p][h], bh[p][h + 1]);
                }
            }
        }
        __syncthreads();
    }

#pragma unroll
    for (int mi = 0; mi < 4; mi++) {
        int rbase = row0 + warp_m * 64 + mi * 16 + (lane >> 2);
        int hw0 = rbase & 4095;
        int hw8 = (rbase + 8) & 4095;
#pragma unroll
        for (int nj = 0; nj < 4; nj++) {
            int c = n0 + warp_n * 32 + nj * 8 + ((lane & 3) << 1);
            float b0 = __ldg(bias + c), b1 = __ldg(bias + c + 1);
            float2 o0, o1;
            o0.x = (acc[mi][nj][0] + b0) * scale;
            o0.y = (acc[mi][nj][1] + b1) * scale;
            o1.x = (acc[mi][nj][2] + b0) * scale;
            o1.y = (acc[mi][nj][3] + b1) * scale;
            if (do_rope) {
                int d0 = c & 31;
                float s0 = __ldg(sinp + hw0 * 32 + d0);
                float s1 = __ldg(sinp + hw0 * 32 + d0 + 1);
                float c0v = __ldg(cosp + hw0 * 32 + d0);
                float c1v = __ldg(cosp + hw0 * 32 + d0 + 1);
                float xe = o0.x, xo = o0.y;
                o0.x = xe * c0v - xo * s0;
                o0.y = xo * c1v + xe * s1;
                float s0b = __ldg(sinp + hw8 * 32 + d0);
                float s1b = __ldg(sinp + hw8 * 32 + d0 + 1);
                float c0b = __ldg(cosp + hw8 * 32 + d0);
                float c1b = __ldg(cosp + hw8 * 32 + d0 + 1);
                float xe1 = o1.x, xo1 = o1.y;
                o1.x = xe1 * c0b - xo1 * s0b;
                o1.y = xo1 * c1b + xe1 * s1b;
            }
            *(float2*)(outp + (size_t)rbase * 256 + c) = o0;
            *(float2*)(outp + (size_t)(rbase + 8) * 256 + c) = o1;
        }
    }
}

// ---------------- LePE depthwise 5x5 conv (sliding window) ----------------
__global__ __launch_bounds__(256) void lepe_kernel(
    const float* __restrict__ lw, const float* __restrict__ lb)
{
    int blk = blockIdx.x;            // (b*64 + h)*2 + whalf
    int whalf = blk & 1;
    int h = (blk >> 1) & 63;
    int b = blk >> 7;
    int c = threadIdx.x;

    float wt[5][5];
    const float* vrow[5];
    bool rv[5];
#pragma unroll
    for (int ki = 0; ki < 5; ki++) {
        int hh = h + ki - 2;
        rv[ki] = ((unsigned)hh < 64u);
        vrow[ki] = g_v + ((size_t)((b * 64 + (rv[ki] ? hh : 0)) * 64)) * 256 + c;
#pragma unroll
        for (int kj = 0; kj < 5; kj++)
            wt[ki][kj] = __ldg(lw + (ki * 5 + kj) * 256 + c);
    }
    float lbv = __ldg(lb + c);

    float win[5][5];
    int w0 = whalf * 32;
#pragma unroll
    for (int dj = 0; dj < 4; dj++) {
        int col = w0 - 2 + dj;
        bool cv = ((unsigned)col < 64u);
#pragma unroll
        for (int ki = 0; ki < 5; ki++)
            win[ki][dj] = (rv[ki] && cv) ? __ldg(vrow[ki] + col * 256) : 0.f;
    }

    float* outb = g_lepe + ((size_t)((b * 64 + h) * 64)) * 256 + c;
    for (int w = w0; w < w0 + 32; w++) {
        int col = w + 2;
        bool cv = (col < 64);
#pragma unroll
        for (int ki = 0; ki < 5; ki++)
            win[ki][4] = (rv[ki] && cv) ? __ldg(vrow[ki] + col * 256) : 0.f;
        float acc = lbv;
#pragma unroll
        for (int ki = 0; ki < 5; ki++)
#pragma unroll
            for (int kj = 0; kj < 5; kj++)
                acc += win[ki][kj] * wt[ki][kj];
        outb[w * 256] = acc;
#pragma unroll
        for (int ki = 0; ki < 5; ki++)
#pragma unroll
            for (int dj = 0; dj < 4; dj++)
                win[ki][dj] = win[ki][dj + 1];
    }
}

// ---------------- attention (mma.sync bf16 hi/lo; trans-ldmatrix B) ----------------
#define AT_QHI 0
#define AT_QLO 5120
#define AT_KHI 10240
#define AT_KLO 15360
#define AT_VHI 20480
#define AT_VLO 25600
#define AT_WHI 30720
#define AT_WLO 35840
#define AT_PHI 0
#define AT_PLO 9216
#define AT_SW  30720
#define AT_CSW 47616
#define ATTN_SMEM_W 47872
#define AT_SH  40960
#define AT_CSH 57856
#define ATTN_SMEM_H 58112

__device__ __forceinline__ void s_phase(uint32_t sbase, int lane, int wid,
                                        float* S, const float* cs)
{
    int wm = wid >> 2, wn = wid & 3;
    uint32_t a_off[2];
#pragma unroll
    for (int mi = 0; mi < 2; mi++) {
        int row = wm * 32 + mi * 16 + (lane & 15);
        int col = ((lane >> 4) & 1) << 3;
        a_off[mi] = (uint32_t)(row * GP + col) * 2;
    }
    int m = lane >> 3;
    uint32_t b_off = (uint32_t)((wn * 16 + ((m >> 1) << 3) + (lane & 7)) * GP + ((m & 1) << 3)) * 2;

    float sacc[2][2][4];
#pragma unroll
    for (int a = 0; a < 2; a++)
#pragma unroll
        for (int b2 = 0; b2 < 2; b2++)
#pragma unroll
            for (int e = 0; e < 4; e++) sacc[a][b2][e] = 0.f;

#pragma unroll
    for (int ks = 0; ks < 2; ks++) {
        uint32_t kb = (uint32_t)(ks * 16) * 2;
        uint32_t ah[2][4], al[2][4], bh[4], bl[4];
#pragma unroll
        for (int mi = 0; mi < 2; mi++) {
            ldm4(sbase + AT_QHI + a_off[mi] + kb, ah[mi][0], ah[mi][1], ah[mi][2], ah[mi][3]);
            ldm4(sbase + AT_QLO + a_off[mi] + kb, al[mi][0], al[mi][1], al[mi][2], al[mi][3]);
        }
        ldm4(sbase + AT_KHI + b_off + kb, bh[0], bh[1], bh[2], bh[3]);
        ldm4(sbase + AT_KLO + b_off + kb, bl[0], bl[1], bl[2], bl[3]);
#pragma unroll
        for (int mi = 0; mi < 2; mi++) {
#pragma unroll
            for (int nj = 0; nj < 2; nj++) {
                int h2 = nj * 2;
                mma16816(sacc[mi][nj], ah[mi], bh[h2], bh[h2 + 1]);
                mma16816(sacc[mi][nj], ah[mi], bl[h2], bl[h2 + 1]);
                mma16816(sacc[mi][nj], al[mi], bh[h2], bh[h2 + 1]);
            }
        }
    }
#pragma unroll
    for (int mi = 0; mi < 2; mi++) {
#pragma unroll
        for (int nj = 0; nj < 2; nj++) {
            int r0 = wm * 32 + mi * 16 + (lane >> 2);
            int c0 = wn * 16 + nj * 8 + ((lane & 3) << 1);
            float cr0 = cs[r0], cr8 = cs[r0 + 8];
            float cc0 = cs[c0], cc1 = cs[c0 + 1];
            S[r0 * 66 + c0]       = sacc[mi][nj][0] + ((r0 >= c0)     ? cr0 - cc0 : cc0 - cr0);
            S[r0 * 66 + c0 + 1]   = sacc[mi][nj][1] + ((r0 >= c0 + 1) ? cr0 - cc1 : cc1 - cr0);
            S[(r0 + 8) * 66 + c0]     = sacc[mi][nj][2] + ((r0 + 8 >= c0)     ? cr8 - cc0 : cc0 - cr8);
            S[(r0 + 8) * 66 + c0 + 1] = sacc[mi][nj][3] + ((r0 + 8 >= c0 + 1) ? cr8 - cc1 : cc1 - cr8);
        }
    }
}

__device__ __forceinline__ void softmax_phase(char* sm, int lane, int wid, float* S)
{
#pragma unroll
    for (int rr = 0; rr < 8; rr++) {
        int i = wid * 8 + rr;
        float v0 = S[i * 66 + lane], v1 = S[i * 66 + lane + 32];
        float mx = fmaxf(v0, v1);
#pragma unroll
        for (int off = 16; off; off >>= 1) mx = fmaxf(mx, __shfl_xor_sync(0xffffffffu, mx, off));
        float e0 = __expf(v0 - mx), e1 = __expf(v1 - mx);
        float s = e0 + e1;
#pragma unroll
        for (int off = 16; off; off >>= 1) s += __shfl_xor_sync(0xffffffffu, s, off);
        float inv = 1.f / s;
        float p0 = e0 * inv, p1 = e1 * inv;
        __nv_bfloat16 h0, l0, h1, l1;
        split1(p0, h0, l0);
        split1(p1, h1, l1);
        *(__nv_bfloat16*)(sm + AT_PHI + (i * 72 + lane) * 2) = h0;
        *(__nv_bfloat16*)(sm + AT_PHI + (i * 72 + lane + 32) * 2) = h1;
        *(__nv_bfloat16*)(sm + AT_PLO + (i * 72 + lane) * 2) = l0;
        *(__nv_bfloat16*)(sm + AT_PLO + (i * 72 + lane + 32) * 2) = l1;
    }
}

__device__ __forceinline__ void pv_phase(uint32_t sbase, int lane, int wid,
                                         uint32_t bhi, uint32_t blo, float facc[2][4])
{
    int wm = wid >> 1, wn = wid & 1;
    uint32_t a_off = (uint32_t)((wm * 16 + (lane & 15)) * 72 + (((lane >> 4) & 1) << 3)) * 2;
    int g = lane >> 3, j8 = lane & 7;
    uint32_t b_off = (uint32_t)(((g & 1) * 8 + j8) * GP + wn * 16 + ((g >> 1) << 3)) * 2;
#pragma unroll
    for (int ks = 0; ks < 4; ks++) {
        uint32_t kbA = (uint32_t)(ks * 16) * 2;
        uint32_t kbB = (uint32_t)(ks * 16 * GP) * 2;
        uint32_t ah[4], al[4], bh[4], bl[4];
        ldm4(sbase + AT_PHI + a_off + kbA, ah[0], ah[1], ah[2], ah[3]);
        ldm4(sbase + AT_PLO + a_off + kbA, al[0], al[1], al[2], al[3]);
        ldm4t(bhi + b_off + kbB, bh[0], bh[1], bh[2], bh[3]);
        ldm4t(blo + b_off + kbB, bl[0], bl[1], bl[2], bl[3]);
#pragma unroll
        for (int nj = 0; nj < 2; nj++) {
            int h2 = nj * 2;
            mma16816(facc[nj], ah, bh[h2], bh[h2 + 1]);
            mma16816(facc[nj], ah, bl[h2], bl[h2 + 1]);
            mma16816(facc[nj], al, bh[h2], bh[h2 + 1]);
        }
    }
}

__global__ __launch_bounds__(256) void attn_w_kernel(void)
{
    extern __shared__ char sm[];
    int blk = blockIdx.x;
    int n = blk & 7;
    int h = (blk >> 3) & 63;
    int b = blk >> 9;
    int tid = threadIdx.x, lane = tid & 31, wid = tid >> 5;
    int qbase = ((b * 64 + h) * 64) * 256 + n * 32;
    float* S = (float*)(sm + AT_SW);
    float* cs = (float*)(sm + AT_CSW);
    uint32_t sbase = smem_u32(sm);

    for (int e = tid; e < 512; e += 256) {
        int i = e >> 3, d4 = (e & 7) << 2;
        float4 qv = *(const float4*)(g_q + qbase + i * 256 + d4);
        float4 kv = *(const float4*)(g_k + qbase + i * 256 + d4);
        float4 vv = *(const float4*)(g_v + qbase + i * 256 + d4);
        uint2 hv, lv;
        uint32_t so = (uint32_t)(i * GP + d4) * 2;
        split4(qv, hv, lv);
        *(uint2*)(sm + AT_QHI + so) = hv; *(uint2*)(sm + AT_QLO + so) = lv;
        split4(kv, hv, lv);
        *(uint2*)(sm + AT_KHI + so) = hv; *(uint2*)(sm + AT_KLO + so) = lv;
        split4(vv, hv, lv);
        *(uint2*)(sm + AT_VHI + so) = hv; *(uint2*)(sm + AT_VLO + so) = lv;
    }
    if (tid == 0) {
        float run = 0.f;
        const float* dap = g_da + blk * 64;
        for (int j = 0; j < 64; j++) { run += dap[j]; cs[j] = run; }
    }
    __syncthreads();

    s_phase(sbase, lane, wid, S, cs);
    __syncthreads();

    softmax_phase(sm, lane, wid, S);
    __syncthreads();

    __nv_bfloat16* gh = g_qkwh + (size_t)blk * 4096;
    __nv_bfloat16* gl = g_qkwl + (size_t)blk * 4096;
    for (int e = tid; e < 512; e += 256) {
        int row = e >> 3, c8 = (e & 7) << 3;
        *(uint4*)(gh + row * 64 + c8) = *(uint4*)(sm + AT_PHI + (row * 72 + c8) * 2);
        *(uint4*)(gl + row * 64 + c8) = *(uint4*)(sm + AT_PLO + (row * 72 + c8) * 2);
    }

    float facc[2][4];
#pragma unroll
    for (int nj = 0; nj < 2; nj++)
#pragma unroll
        for (int e = 0; e < 4; e++) facc[nj][e] = 0.f;
    pv_phase(sbase, lane, wid, sbase + AT_VHI, sbase + AT_VLO, facc);

    float* vwp = g_vw + (size_t)blk * 2048;
    int wm = wid >> 1, wn = wid & 1;
#pragma unroll
    for (int nj = 0; nj < 2; nj++) {
        int r0 = wm * 16 + (lane >> 2);
        int d0 = wn * 16 + nj * 8 + ((lane & 3) << 1);
        float2 o0 = {facc[nj][0], facc[nj][1]};
        float2 o1 = {facc[nj][2], facc[nj][3]};
        *(float2*)(vwp + r0 * 32 + d0) = o0;
        *(float2*)(vwp + (r0 + 8) * 32 + d0) = o1;
    }
}

__global__ __launch_bounds__(256) void attn_h_kernel(void)
{
    extern __shared__ char sm[];
    int blk = blockIdx.x;
    int n = blk & 7;
    int x = (blk >> 3) & 63;
    int b = blk >> 9;
    int tid = threadIdx.x, lane = tid & 31, wid = tid >> 5;
    int qbase = (b * 64 * 64 + x) * 256 + n * 32;
    float* S = (float*)(sm + AT_SH);
    float* cs = (float*)(sm + AT_CSH);
    uint32_t sbase = smem_u32(sm);

    for (int e = tid; e < 512; e += 256) {
        int i = e >> 3, d4 = (e & 7) << 2;
        float4 qv = *(const float4*)(g_q + qbase + i * 16384 + d4);
        float4 kv = *(const float4*)(g_k + qbase + i * 16384 + d4);
        float4 vv = *(const float4*)(g_v + qbase + i * 16384 + d4);
        float4 wv = *(const float4*)(g_vw + ((size_t)((b * 64 + i) * 8 + n)) * 2048 + x * 32 + d4);
        uint2 hv, lv;
        uint32_t so = (uint32_t)(i * GP + d4) * 2;
        split4(qv, hv, lv);
        *(uint2*)(sm + AT_QHI + so) = hv; *(uint2*)(sm + AT_QLO + so) = lv;
        split4(kv, hv, lv);
        *(uint2*)(sm + AT_KHI + so) = hv; *(uint2*)(sm + AT_KLO + so) = lv;
        split4(vv, hv, lv);
        *(uint2*)(sm + AT_VHI + so) = hv; *(uint2*)(sm + AT_VLO + so) = lv;
        split4(wv, hv, lv);
        *(uint2*)(sm + AT_WHI + so) = hv; *(uint2*)(sm + AT_WLO + so) = lv;
    }
    if (tid == 0) {
        float run = 0.f;
        const float* dbp = g_db + blk * 64;
        for (int j = 0; j < 64; j++) { run += dbp[j]; cs[j] = run; }
    }
    __syncthreads();

    s_phase(sbase, lane, wid, S, cs);
    __syncthreads();

    softmax_phase(sm, lane, wid, S);
    __syncthreads();

    float facc1[2][4], facc2[2][4];
#pragma unroll
    for (int nj = 0; nj < 2; nj++)
#pragma unroll
        for (int e = 0; e < 4; e++) { facc1[nj][e] = 0.f; facc2[nj][e] = 0.f; }
    pv_phase(sbase, lane, wid, sbase + AT_VHI, sbase + AT_VLO, facc1);
    pv_phase(sbase, lane, wid, sbase + AT_WHI, sbase + AT_WLO, facc2);

    float* v2p = g_vh2 + (size_t)blk * 2048;
    int wm = wid >> 1, wn = wid & 1;
#pragma unroll
    for (int nj = 0; nj < 2; nj++) {
        int r0 = wm * 16 + (lane >> 2);
        int d0 = wn * 16 + nj * 8 + ((lane & 3) << 1);
        float2 o0 = {facc1[nj][0], facc1[nj][1]};
        float2 o1 = {facc1[nj][2], facc1[nj][3]};
        *(float2*)(v2p + r0 * 32 + d0) = o0;
        *(float2*)(v2p + (r0 + 8) * 32 + d0) = o1;
        float2 p0 = {0.5f * facc2[nj][0], 0.5f * facc2[nj][1]};
        float2 p1 = {0.5f * facc2[nj][2], 0.5f * facc2[nj][3]};
        *(float2*)(g_pre + (size_t)((b * 64 + r0) * 64 + x) * 256 + n * 32 + d0) = p0;
        *(float2*)(g_pre + (size_t)((b * 64 + r0 + 8) * 64 + x) * 256 + n * 32 + d0) = p1;
    }
}

// out2: final = pre + 0.5*(qk_w @ v_h2) + lepe -> bf16 hi/lo split (for final GEMM)
#define O2_PHI 0
#define O2_PLO 9216
#define O2_VHI 18432
#define O2_VLO 23552
#define OUT2_SMEM 28672

__global__ __launch_bounds__(256) void out2_kernel(void)
{
    extern __shared__ char sm[];
    int blk = blockIdx.x;
    int n = blk & 7;
    int y = (blk >> 3) & 63;
    int b = blk >> 9;
    int tid = threadIdx.x, lane = tid & 31, wid = tid >> 5;
    uint32_t sbase = smem_u32(sm);

    const __nv_bfloat16* gh = g_qkwh + (size_t)blk * 4096;
    const __nv_bfloat16* gl = g_qkwl + (size_t)blk * 4096;
    for (int e = tid; e < 512; e += 256) {
        int row = e >> 3, c8 = (e & 7) << 3;
        *(uint4*)(sm + O2_PHI + (row * 72 + c8) * 2) = *(const uint4*)(gh + row * 64 + c8);
        *(uint4*)(sm + O2_PLO + (row * 72 + c8) * 2) = *(const uint4*)(gl + row * 64 + c8);
    }
    for (int e = tid; e < 512; e += 256) {
        int j = e >> 3, d4 = (e & 7) << 2;
        float4 vv = *(const float4*)(g_vh2 + ((size_t)((b * 64 + j) * 8 + n)) * 2048 + y * 32 + d4);
        uint2 hv, lv;
        split4(vv, hv, lv);
        uint32_t so = (uint32_t)(j * GP + d4) * 2;
        *(uint2*)(sm + O2_VHI + so) = hv;
        *(uint2*)(sm + O2_VLO + so) = lv;
    }
    __syncthreads();

    int wm = wid >> 1, wn = wid & 1;
    uint32_t a_off = (uint32_t)((wm * 16 + (lane & 15)) * 72 + (((lane >> 4) & 1) << 3)) * 2;
    int g = lane >> 3, j8 = lane & 7;
    uint32_t b_off = (uint32_t)(((g & 1) * 8 + j8) * GP + wn * 16 + ((g >> 1) << 3)) * 2;
    float facc[2][4];
#pragma unroll
    for (int nj = 0; nj < 2; nj++)
#pragma unroll
        for (int e = 0; e < 4; e++) facc[nj][e] = 0.f;
#pragma unroll
    for (int ks = 0; ks < 4; ks++) {
        uint32_t kbA = (uint32_t)(ks * 16) * 2;
        uint32_t kbB = (uint32_t)(ks * 16 * GP) * 2;
        uint32_t ah[4], al[4], bh[4], bl[4];
        ldm4(sbase + O2_PHI + a_off + kbA, ah[0], ah[1], ah[2], ah[3]);
        ldm4(sbase + O2_PLO + a_off + kbA, al[0], al[1], al[2], al[3]);
        ldm4t(sbase + O2_VHI + b_off + kbB, bh[0], bh[1], bh[2], bh[3]);
        ldm4t(sbase + O2_VLO + b_off + kbB, bl[0], bl[1], bl[2], bl[3]);
#pragma unroll
        for (int nj = 0; nj < 2; nj++) {
            int h2 = nj * 2;
            mma16816(facc[nj], ah, bh[h2], bh[h2 + 1]);
            mma16816(facc[nj], ah, bl[h2], bl[h2 + 1]);
            mma16816(facc[nj], al, bh[h2], bh[h2 + 1]);
        }
    }

#pragma unroll
    for (int nj = 0; nj < 2; nj++) {
        int r0 = wm * 16 + (lane >> 2);
        int d0 = wn * 16 + nj * 8 + ((lane & 3) << 1);
        size_t a0 = (size_t)((b * 64 + y) * 64 + r0) * 256 + n * 32 + d0;
        size_t a1 = (size_t)((b * 64 + y) * 64 + r0 + 8) * 256 + n * 32 + d0;
        float2 pr0 = *(float2*)(g_pre + a0);
        float2 le0 = *(float2*)(g_lepe + a0);
        float2 pr1 = *(float2*)(g_pre + a1);
        float2 le1 = *(float2*)(g_lepe + a1);
        float fx0 = pr0.x + 0.5f * facc[nj][0] + le0.x;
        float fy0 = pr0.y + 0.5f * facc[nj][1] + le0.y;
        float fx1 = pr1.x + 0.5f * facc[nj][2] + le1.x;
        float fy1 = pr1.y + 0.5f * facc[nj][3] + le1.y;
        __nv_bfloat16 hx0, lx0, hy0, ly0, hx1, lx1, hy1, ly1;
        split1(fx0, hx0, lx0); split1(fy0, hy0, ly0);
        split1(fx1, hx1, lx1); split1(fy1, hy1, ly1);
        *(uint32_t*)(g_ahi + a0) = (uint32_t)__bfloat16_as_ushort(hx0)
                                 | ((uint32_t)__bfloat16_as_ushort(hy0) << 16);
        *(uint32_t*)(g_alo + a0) = (uint32_t)__bfloat16_as_ushort(lx0)
                                 | ((uint32_t)__bfloat16_as_ushort(ly0) << 16);
        *(uint32_t*)(g_ahi + a1) = (uint32_t)__bfloat16_as_ushort(hx1)
                                 | ((uint32_t)__bfloat16_as_ushort(hy1) << 16);
        *(uint32_t*)(g_alo + a1) = (uint32_t)__bfloat16_as_ushort(lx1)
                                 | ((uint32_t)__bfloat16_as_ushort(ly1) << 16);
    }
}

// ---------------- launch ----------------
extern "C" void kernel_launch(void* const* d_in, const int* in_sizes, int n_in,
                              void* d_out, int out_size)
{
    const float* x    = (const float*)d_in[0];
    const float* sinp = (const float*)d_in[1];
    const float* cosp = (const float*)d_in[2];
    const float* Wq   = (const float*)d_in[3];
    const float* bq   = (const float*)d_in[4];
    const float* Wk   = (const float*)d_in[5];
    const float* bk   = (const float*)d_in[6];
    const float* Wv   = (const float*)d_in[7];
    const float* bv   = (const float*)d_in[8];
    const float* Wo   = (const float*)d_in[9];
    const float* bo   = (const float*)d_in[10];
    const float* lw   = (const float*)d_in[11];
    const float* lb   = (const float*)d_in[12];
    const float* dtw  = (const float*)d_in[13];
    const float* dtb  = (const float*)d_in[14];
    const float* Alog = (const float*)d_in[15];
    float* out = (float*)d_out;

    const float scaling = 0.17677669529663687f;   // 32^-0.5

    cudaFuncSetAttribute(gemm_mma_kernel,
                         cudaFuncAttributeMaxDynamicSharedMemorySize, GEMM_SMEM);
    cudaFuncSetAttribute(attn_w_kernel,
                         cudaFuncAttributeMaxDynamicSharedMemorySize, ATTN_SMEM_W);
    cudaFuncSetAttribute(attn_h_kernel,
                         cudaFuncAttributeMaxDynamicSharedMemorySize, ATTN_SMEM_H);
    cudaFuncSetAttribute(out2_kernel,
                         cudaFuncAttributeMaxDynamicSharedMemorySize, OUT2_SMEM);

    convW_kernel<<<dim3(64, 4), 256>>>(Wq, Wk, Wv, Wo);               // 0
    dtconv_kernel<<<NROW / 4, 256>>>(x, dtw, dtb, Alog);              // 1 (x split + dt)

    gemm_mma_kernel<<<dim3(6, 512), 256, GEMM_SMEM>>>(
        bq, bk, bv, nullptr, 0, scaling, sinp, cosp);                 // 2 (fused q/k/v)

    lepe_kernel<<<Bn * Hn * 2, 256>>>(lw, lb);                        // 3

    attn_w_kernel<<<Bn * Hn * Nn, 256, ATTN_SMEM_W>>>();              // 4
    attn_h_kernel<<<Bn * Wn * Nn, 256, ATTN_SMEM_H>>>();              // 5 <- profiled
    out2_kernel<<<Bn * Hn * Nn, 256, OUT2_SMEM>>>();                  // 6

    gemm_mma_kernel<<<dim3(2, 512), 256, GEMM_SMEM>>>(
        bo, nullptr, nullptr, out, 1, 1.0f, sinp, cosp);              // 7 (output proj)
}

// round 11
// speedup vs baseline: 1.8312x; 1.1479x over previous
#include <cuda_runtime.h>
#include <cuda_bf16.h>
#include <math.h>
#include <stdint.h>

#define Bn 16
#define Hn 64
#define Wn 64
#define Cn 256
#define Nn 8
#define Dn 32
#define NROW (Bn*Hn*Wn)   // 65536

// ---------------- scratch (device globals; no allocation) ----------------
__device__ float g_q[NROW*Cn];
__device__ float g_k[NROW*Cn];
__device__ float g_v[NROW*Cn];
__device__ float g_lepe[NROW*Cn];
__device__ float g_pre[NROW*Cn];
__device__ float g_vw[Bn*Hn*Nn*64*32];       // [b][h][n][w][d]
__device__ float g_vh2[Bn*Wn*Nn*64*32];      // [b][w][n][h][d]
__device__ float g_da[Bn*Hn*Nn*Wn];
__device__ float g_db[Bn*Wn*Nn*Hn];
// P in MMA-fragment order: [blk][warp(4)][nj(8)][reg(2)][lane(32)] uint32 (bf16x2)
__device__ uint32_t g_qkwh[Bn*Hn*Nn*2048];
__device__ uint32_t g_qkwl[Bn*Hn*Nn*2048];

// bf16 hi/lo split buffers for projection GEMMs
__device__ __nv_bfloat16 g_ahi[NROW*Cn];
__device__ __nv_bfloat16 g_alo[NROW*Cn];
__device__ __nv_bfloat16 g_whi[4*Cn*Cn];
__device__ __nv_bfloat16 g_wlo[4*Cn*Cn];

// ---------------- helpers ----------------
__device__ __forceinline__ uint32_t smem_u32(const void* p) {
    uint32_t a;
    asm("{ .reg .u64 t; cvta.to.shared.u64 t, %1; cvt.u32.u64 %0, t; }"
        : "=r"(a) : "l"(p));
    return a;
}

__device__ __forceinline__ uint32_t pack_bf2(float a, float b) {
    return (uint32_t)__bfloat16_as_ushort(__float2bfloat16_rn(a))
         | ((uint32_t)__bfloat16_as_ushort(__float2bfloat16_rn(b)) << 16);
}

__device__ __forceinline__ void split4(float4 a, uint2& hv, uint2& lv) {
    float h0 = __bfloat162float(__float2bfloat16_rn(a.x));
    float h1 = __bfloat162float(__float2bfloat16_rn(a.y));
    float h2 = __bfloat162float(__float2bfloat16_rn(a.z));
    float h3 = __bfloat162float(__float2bfloat16_rn(a.w));
    hv.x = pack_bf2(a.x, a.y);
    hv.y = pack_bf2(a.z, a.w);
    lv.x = pack_bf2(a.x - h0, a.y - h1);
    lv.y = pack_bf2(a.z - h2, a.w - h3);
}

__device__ __forceinline__ void split1(float v, __nv_bfloat16& h, __nv_bfloat16& l) {
    h = __float2bfloat16_rn(v);
    l = __float2bfloat16_rn(v - __bfloat162float(h));
}

// split two floats -> packed hi bf16x2 (ret) and packed lo bf16x2 (out param)
__device__ __forceinline__ uint32_t packsplit(float a, float b, uint32_t& lo) {
    __nv_bfloat16 ha, la, hb, lb;
    split1(a, ha, la);
    split1(b, hb, lb);
    lo = (uint32_t)__bfloat16_as_ushort(la) | ((uint32_t)__bfloat16_as_ushort(lb) << 16);
    return (uint32_t)__bfloat16_as_ushort(ha) | ((uint32_t)__bfloat16_as_ushort(hb) << 16);
}

__device__ __forceinline__ void ldm4(uint32_t addr, uint32_t& r0, uint32_t& r1,
                                     uint32_t& r2, uint32_t& r3) {
    asm volatile("ldmatrix.sync.aligned.m8n8.x4.shared.b16 {%0,%1,%2,%3}, [%4];"
                 : "=r"(r0), "=r"(r1), "=r"(r2), "=r"(r3) : "r"(addr));
}

__device__ __forceinline__ void ldm4t(uint32_t addr, uint32_t& r0, uint32_t& r1,
                                      uint32_t& r2, uint32_t& r3) {
    asm volatile("ldmatrix.sync.aligned.m8n8.x4.trans.shared.b16 {%0,%1,%2,%3}, [%4];"
                 : "=r"(r0), "=r"(r1), "=r"(r2), "=r"(r3) : "r"(addr));
}

__device__ __forceinline__ void mma16816(float* d, const uint32_t* a,
                                         uint32_t b0, uint32_t b1) {
    asm volatile("mma.sync.aligned.m16n8k16.row.col.f32.bf16.bf16.f32 "
                 "{%0,%1,%2,%3}, {%4,%5,%6,%7}, {%8,%9}, {%0,%1,%2,%3};"
                 : "+f"(d[0]), "+f"(d[1]), "+f"(d[2]), "+f"(d[3])
                 : "r"(a[0]), "r"(a[1]), "r"(a[2]), "r"(a[3]), "r"(b0), "r"(b1));
}

#define CPA16(dst, src) \
    asm volatile("cp.async.cg.shared.global [%0], [%1], 16;" \
                 :: "r"(dst), "l"(src) : "memory")

// ------------- fused: x -> bf16 hi/lo split  +  dt -> da/db -------------
__device__ __forceinline__ float softplusf(float a) {
    return (a > 20.f) ? a : log1pf(expf(a));
}

__global__ __launch_bounds__(256) void dtconv_kernel(
    const float* __restrict__ x, const float* __restrict__ dtw,
    const float* __restrict__ dtb, const float* __restrict__ Alog)
{
    int tid = threadIdx.x;
    int row_local = tid >> 6;
    int lane = tid & 31;
    int t64 = tid & 63;
    int c4 = t64 << 2;
    int r = blockIdx.x * 4 + row_local;
    size_t idx = (size_t)r * 256 + c4;

    float4 v = *(const float4*)(x + idx);
    uint2 hv, lv; split4(v, hv, lv);
    *(uint2*)(g_ahi + idx) = hv;
    *(uint2*)(g_alo + idx) = lv;

    int d4 = c4 & 31;
    float t0 = v.x * dtw[d4] + v.y * dtw[d4 + 1] + v.z * dtw[d4 + 2] + v.w * dtw[d4 + 3];
    float t1 = v.x * dtw[32 + d4] + v.y * dtw[32 + d4 + 1]
             + v.z * dtw[32 + d4 + 2] + v.w * dtw[32 + d4 + 3];
#pragma unroll
    for (int off = 4; off; off >>= 1) {
        t0 += __shfl_down_sync(0xffffffffu, t0, off);
        t1 += __shfl_down_sync(0xffffffffu, t1, off);
    }
    if ((lane & 7) == 0) {
        int n = t64 >> 3;
        int w = r & 63, h = (r >> 6) & 63, b = r >> 12;
        float bias = dtb[n];
        float Aa = -expf(Alog[n]);
        float da = softplusf(t0 + bias) * Aa;
        float db = softplusf(t1 + bias) * Aa;
        g_da[((b * 64 + h) * 8 + n) * 64 + w] = da;
        g_db[((b * 64 + w) * 8 + n) * 64 + h] = db;
    }
}

__global__ __launch_bounds__(256) void convW_kernel(
    const float* __restrict__ wq, const float* __restrict__ wk,
    const float* __restrict__ wv, const float* __restrict__ wo)
{
    const float* src = (blockIdx.y == 0) ? wq : (blockIdx.y == 1) ? wk
                     : (blockIdx.y == 2) ? wv : wo;
    size_t base = (size_t)blockIdx.y * 65536;
    size_t i = ((size_t)blockIdx.x * 256 + threadIdx.x) * 4;
    float4 v = *(const float4*)(src + i);
    uint2 hv, lv; split4(v, hv, lv);
    *(uint2*)(g_whi + base + i) = hv;
    *(uint2*)(g_wlo + base + i) = lv;
}

// ------------- projection GEMM (unchanged from R9) -------------
#define GP 40
#define GMAT 10240
#define GSTG 40960
#define GEMM_SMEM (2*GSTG)

__global__ __launch_bounds__(256, 2) void gemm_mma_kernel(
    const float* __restrict__ b0p, const float* __restrict__ b1p,
    const float* __restrict__ b2p, float* __restrict__ dout,
    int mode, float scaleK,
    const float* __restrict__ sinp, const float* __restrict__ cosp)
{
    extern __shared__ char gsm[];
    int z, col;
    if (mode == 0) { z = blockIdx.x >> 1; col = blockIdx.x & 1; }
    else           { z = 3;               col = blockIdx.x; }
    float* outp;
    const float* bias;
    float scale = 1.0f;
    bool do_rope = false;
    if (mode == 0) {
        if (z == 0)      { outp = g_q; bias = b0p; do_rope = true; }
        else if (z == 1) { outp = g_k; bias = b1p; do_rope = true; scale = scaleK; }
        else             { outp = g_v; bias = b2p; }
    } else { outp = dout; bias = b0p; }
    const __nv_bfloat16* Whi = g_whi + (size_t)z * 65536;
    const __nv_bfloat16* Wlo = g_wlo + (size_t)z * 65536;

    int tid = threadIdx.x;
    int lane = tid & 31, wid = tid >> 5;
    int warp_m = wid >> 2, warp_n = wid & 3;
    int row0 = blockIdx.y * 128;
    int n0 = col * 128;

    int r0i = tid >> 2, q0 = tid & 3;
    int r1i = (tid + 256) >> 2, q1 = tid & 3;
    uint32_t st0 = (uint32_t)(r0i * GP + q0 * 8) * 2;
    uint32_t st1 = (uint32_t)(r1i * GP + q1 * 8) * 2;
    uint32_t gsb = smem_u32(gsm);

    float acc[4][4][4];
#pragma unroll
    for (int i = 0; i < 4; i++)
#pragma unroll
        for (int j = 0; j < 4; j++)
#pragma unroll
            for (int e = 0; e < 4; e++) acc[i][j][e] = 0.f;

    uint32_t a_off[4], b_off[2];
#pragma unroll
    for (int mi = 0; mi < 4; mi++) {
        int row = warp_m * 64 + mi * 16 + (lane & 15);
        int colb = ((lane >> 4) & 1) << 3;
        a_off[mi] = (uint32_t)(row * GP + colb) * 2;
    }
#pragma unroll
    for (int p = 0; p < 2; p++) {
        int m = lane >> 3;
        int nrow = warp_n * 32 + p * 16 + ((m >> 1) << 3) + (lane & 7);
        int colb = (m & 1) << 3;
        b_off[p] = (uint32_t)(nrow * GP + colb) * 2;
    }

    auto issue = [&](int kc) {
        uint32_t sb = gsb + (kc & 1) * GSTG;
        int kn = kc * 32;
        size_t a0 = (size_t)(row0 + r0i) * 256 + kn + q0 * 8;
        size_t a1 = (size_t)(row0 + r1i) * 256 + kn + q1 * 8;
        size_t b0 = (size_t)(n0 + r0i) * 256 + kn + q0 * 8;
        size_t b1 = (size_t)(n0 + r1i) * 256 + kn + q1 * 8;
        CPA16(sb + 0*GMAT + st0, (const void*)(g_ahi + a0));
        CPA16(sb + 0*GMAT + st1, (const void*)(g_ahi + a1));
        CPA16(sb + 1*GMAT + st0, (const void*)(g_alo + a0));
        CPA16(sb + 1*GMAT + st1, (const void*)(g_alo + a1));
        CPA16(sb + 2*GMAT + st0, (const void*)(Whi + b0));
        CPA16(sb + 2*GMAT + st1, (const void*)(Whi + b1));
        CPA16(sb + 3*GMAT + st0, (const void*)(Wlo + b0));
        CPA16(sb + 3*GMAT + st1, (const void*)(Wlo + b1));
        asm volatile("cp.async.commit_group;" ::: "memory");
    };

    issue(0);
    for (int kc = 0; kc < 8; kc++) {
        if (kc < 7) {
            issue(kc + 1);
            asm volatile("cp.async.wait_group 1;" ::: "memory");
        } else {
            asm volatile("cp.async.wait_group 0;" ::: "memory");
        }
        __syncthreads();
        uint32_t sb = gsb + (kc & 1) * GSTG;
#pragma unroll
        for (int ks = 0; ks < 2; ks++) {
            uint32_t kb = (uint32_t)(ks * 16) * 2;
            uint32_t bh[2][4], bl[2][4];
#pragma unroll
            for (int p = 0; p < 2; p++) {
                ldm4(sb + 2*GMAT + b_off[p] + kb, bh[p][0], bh[p][1], bh[p][2], bh[p][3]);
                ldm4(sb + 3*GMAT + b_off[p] + kb, bl[p][0], bl[p][1], bl[p][2], bl[p][3]);
            }
#pragma unroll
            for (int mi = 0; mi < 4; mi++) {
                uint32_t ah[4], al[4];
                ldm4(sb + 0*GMAT + a_off[mi] + kb, ah[0], ah[1], ah[2], ah[3]);
                ldm4(sb + 1*GMAT + a_off[mi] + kb, al[0], al[1], al[2], al[3]);
#pragma unroll
                for (int nj = 0; nj < 4; nj++) {
                    int p = nj >> 1, h = (nj & 1) << 1;
                    mma16816(acc[mi][nj], ah, bh[p][h], bh[p][h + 1]);
                    mma16816(acc[mi][nj], ah, bl[p][h], bl[p][h + 1]);
                    mma16816(acc[mi][nj], al, bh[p][h], bh[p][h + 1]);
                }
            }
        }
        __syncthreads();
    }

#pragma unroll
    for (int mi = 0; mi < 4; mi++) {
        int rbase = row0 + warp_m * 64 + mi * 16 + (lane >> 2);
        int hw0 = rbase & 4095;
        int hw8 = (rbase + 8) & 4095;
#pragma unroll
        for (int nj = 0; nj < 4; nj++) {
            int c = n0 + warp_n * 32 + nj * 8 + ((lane & 3) << 1);
            float b0 = __ldg(bias + c), b1 = __ldg(bias + c + 1);
            float2 o0, o1;
            o0.x = (acc[mi][nj][0] + b0) * scale;
            o0.y = (acc[mi][nj][1] + b1) * scale;
            o1.x = (acc[mi][nj][2] + b0) * scale;
            o1.y = (acc[mi][nj][3] + b1) * scale;
            if (do_rope) {
                int d0 = c & 31;
                float s0 = __ldg(sinp + hw0 * 32 + d0);
                float s1 = __ldg(sinp + hw0 * 32 + d0 + 1);
                float c0v = __ldg(cosp + hw0 * 32 + d0);
                float c1v = __ldg(cosp + hw0 * 32 + d0 + 1);
                float xe = o0.x, xo = o0.y;
                o0.x = xe * c0v - xo * s0;
                o0.y = xo * c1v + xe * s1;
                float s0b = __ldg(sinp + hw8 * 32 + d0);
                float s1b = __ldg(sinp + hw8 * 32 + d0 + 1);
                float c0b = __ldg(cosp + hw8 * 32 + d0);
                float c1b = __ldg(cosp + hw8 * 32 + d0 + 1);
                float xe1 = o1.x, xo1 = o1.y;
                o1.x = xe1 * c0b - xo1 * s0b;
                o1.y = xo1 * c1b + xe1 * s1b;
            }
            *(float2*)(outp + (size_t)rbase * 256 + c) = o0;
            *(float2*)(outp + (size_t)(rbase + 8) * 256 + c) = o1;
        }
    }
}

// ---------------- LePE depthwise 5x5 conv (full unroll, rotating window) ----------------
__global__ __launch_bounds__(256) void lepe_kernel(
    const float* __restrict__ lw, const float* __restrict__ lb)
{
    int blk = blockIdx.x;            // (b*64 + h)*2 + whalf
    int whalf = blk & 1;
    int h = (blk >> 1) & 63;
    int b = blk >> 7;
    int c = threadIdx.x;

    float wt[5][5];
    const float* vrow[5];
    bool rv[5];
#pragma unroll
    for (int ki = 0; ki < 5; ki++) {
        int hh = h + ki - 2;
        rv[ki] = ((unsigned)hh < 64u);
        vrow[ki] = g_v + ((size_t)((b * 64 + (rv[ki] ? hh : 0)) * 64)) * 256 + c;
#pragma unroll
        for (int kj = 0; kj < 5; kj++)
            wt[ki][kj] = __ldg(lw + (ki * 5 + kj) * 256 + c);
    }
    float lbv = __ldg(lb + c);

    float win[5][5];
    int w0 = whalf * 32;
#pragma unroll
    for (int dj = 0; dj < 4; dj++) {
        int col = w0 - 2 + dj;
        bool cv = ((unsigned)col < 64u);
#pragma unroll
        for (int ki = 0; ki < 5; ki++)
            win[ki][dj] = (rv[ki] && cv) ? __ldg(vrow[ki] + col * 256) : 0.f;
    }

    float* outb = g_lepe + ((size_t)((b * 64 + h) * 64)) * 256 + c;
#pragma unroll
    for (int it = 0; it < 32; it++) {
        int w = w0 + it;
        int col = w + 2;
        bool cv = (col < 64);
        const int slot = (it + 4) % 5;
#pragma unroll
        for (int ki = 0; ki < 5; ki++)
            win[ki][slot] = (rv[ki] && cv) ? __ldg(vrow[ki] + col * 256) : 0.f;
        float acc = lbv;
#pragma unroll
        for (int ki = 0; ki < 5; ki++)
#pragma unroll
            for (int kj = 0; kj < 5; kj++)
                acc += win[ki][(it + kj) % 5] * wt[ki][kj];
        outb[w * 256] = acc;
    }
}

// ---------------- attention: 4-warp register-resident S/P ----------------
#define AQ_HI 0
#define AQ_LO 5120
#define AK_HI 10240
#define AK_LO 15360
#define AV_HI 20480
#define AV_LO 25600
#define AW_HI 30720
#define AW_LO 35840
#define W_CS  30720
#define H_CS  40960
#define ATTN_SMEM_W 30976
#define ATTN_SMEM_H 41216

// S = Q K^T into registers; warp w owns rows 16w..16w+15, all 64 cols
__device__ __forceinline__ void s_reg(uint32_t sbase, int lane, int w, float sacc[8][4])
{
    uint32_t a_off = (uint32_t)((w * 16 + (lane & 15)) * GP + (((lane >> 4) & 1) << 3)) * 2;
    int m = lane >> 3;
    uint32_t b_base = (uint32_t)((((m >> 1) << 3) + (lane & 7)) * GP + ((m & 1) << 3)) * 2;
#pragma unroll
    for (int ks = 0; ks < 2; ks++) {
        uint32_t kb = (uint32_t)ks * 32;
        uint32_t ah[4], al[4];
        ldm4(sbase + AQ_HI + a_off + kb, ah[0], ah[1], ah[2], ah[3]);
        ldm4(sbase + AQ_LO + a_off + kb, al[0], al[1], al[2], al[3]);
#pragma unroll
        for (int jb = 0; jb < 4; jb++) {
            uint32_t boff = b_base + (uint32_t)(jb * 16 * GP) * 2 + kb;
            uint32_t bh[4], bl[4];
            ldm4(sbase + AK_HI + boff, bh[0], bh[1], bh[2], bh[3]);
            ldm4(sbase + AK_LO + boff, bl[0], bl[1], bl[2], bl[3]);
#pragma unroll
            for (int half = 0; half < 2; half++) {
                float* d = sacc[jb * 2 + half];
                int h2 = half * 2;
                mma16816(d, ah, bh[h2], bh[h2 + 1]);
                mma16816(d, ah, bl[h2], bl[h2 + 1]);
                mma16816(d, al, bh[h2], bh[h2 + 1]);
            }
        }
    }
}

// mask + softmax in registers (per thread: rows r0=w*16+gr, r1=r0+8)
__device__ __forceinline__ void mask_softmax_reg(int lane, int w, const float* cs,
                                                 float sacc[8][4])
{
    int gr = lane >> 2, gc2 = (lane & 3) << 1;
    int r0 = w * 16 + gr, r1 = r0 + 8;
    float cr0 = cs[r0], cr1 = cs[r1];
#pragma unroll
    for (int nj = 0; nj < 8; nj++) {
        int c0 = nj * 8 + gc2;
        float cc0 = cs[c0], cc1 = cs[c0 + 1];
        sacc[nj][0] += (r0 >= c0)     ? cr0 - cc0 : cc0 - cr0;
        sacc[nj][1] += (r0 >= c0 + 1) ? cr0 - cc1 : cc1 - cr0;
        sacc[nj][2] += (r1 >= c0)     ? cr1 - cc0 : cc0 - cr1;
        sacc[nj][3] += (r1 >= c0 + 1) ? cr1 - cc1 : cc1 - cr1;
    }
    float m0 = -1e30f, m1 = -1e30f;
#pragma unroll
    for (int nj = 0; nj < 8; nj++) {
        m0 = fmaxf(m0, fmaxf(sacc[nj][0], sacc[nj][1]));
        m1 = fmaxf(m1, fmaxf(sacc[nj][2], sacc[nj][3]));
    }
    m0 = fmaxf(m0, __shfl_xor_sync(0xffffffffu, m0, 1));
    m0 = fmaxf(m0, __shfl_xor_sync(0xffffffffu, m0, 2));
    m1 = fmaxf(m1, __shfl_xor_sync(0xffffffffu, m1, 1));
    m1 = fmaxf(m1, __shfl_xor_sync(0xffffffffu, m1, 2));
    float s0 = 0.f, s1 = 0.f;
#pragma unroll
    for (int nj = 0; nj < 8; nj++) {
        sacc[nj][0] = __expf(sacc[nj][0] - m0); s0 += sacc[nj][0];
        sacc[nj][1] = __expf(sacc[nj][1] - m0); s0 += sacc[nj][1];
        sacc[nj][2] = __expf(sacc[nj][2] - m1); s1 += sacc[nj][2];
        sacc[nj][3] = __expf(sacc[nj][3] - m1); s1 += sacc[nj][3];
    }
    s0 += __shfl_xor_sync(0xffffffffu, s0, 1);
    s0 += __shfl_xor_sync(0xffffffffu, s0, 2);
    s1 += __shfl_xor_sync(0xffffffffu, s1, 1);
    s1 += __shfl_xor_sync(0xffffffffu, s1, 2);
    float i0 = 1.f / s0, i1 = 1.f / s1;
#pragma unroll
    for (int nj = 0; nj < 8; nj++) {
        sacc[nj][0] *= i0; sacc[nj][1] *= i0;
        sacc[nj][2] *= i1; sacc[nj][3] *= i1;
    }
}

// P (registers) @ V (smem, row-major pitch GP, trans ldmatrix); out 16x32 per warp
__device__ __forceinline__ void pv_reg(uint32_t bhi, uint32_t blo, int lane,
                                       const uint32_t ph[8][2], const uint32_t pl[8][2],
                                       float facc[4][4])
{
    int g = lane >> 3, j8 = lane & 7;
    uint32_t b_base = (uint32_t)(((g & 1) * 8 + j8) * GP + ((g >> 1) << 3)) * 2;
#pragma unroll
    for (int kc = 0; kc < 4; kc++) {
        uint32_t ah[4] = {ph[2*kc][0], ph[2*kc][1], ph[2*kc+1][0], ph[2*kc+1][1]};
        uint32_t al[4] = {pl[2*kc][0], pl[2*kc][1], pl[2*kc+1][0], pl[2*kc+1][1]};
        uint32_t krow = (uint32_t)(kc * 16 * GP) * 2;
#pragma unroll
        for (int cg = 0; cg < 2; cg++) {
            uint32_t boff = b_base + krow + (uint32_t)(cg * 16) * 2;
            uint32_t bh[4], bl[4];
            ldm4t(bhi + boff, bh[0], bh[1], bh[2], bh[3]);
            ldm4t(blo + boff, bl[0], bl[1], bl[2], bl[3]);
#pragma unroll
            for (int half = 0; half < 2; half++) {
                float* d = facc[cg * 2 + half];
                int h2 = half * 2;
                mma16816(d, ah, bh[h2], bh[h2 + 1]);
                mma16816(d, ah, bl[h2], bl[h2 + 1]);
                mma16816(d, al, bh[h2], bh[h2 + 1]);
            }
        }
    }
}

__global__ __launch_bounds__(128) void attn_w_kernel(void)
{
    extern __shared__ char sm[];
    int blk = blockIdx.x;
    int n = blk & 7;
    int h = (blk >> 3) & 63;
    int b = blk >> 9;
    int tid = threadIdx.x, lane = tid & 31, w = tid >> 5;
    int qbase = ((b * 64 + h) * 64) * 256 + n * 32;
    float* cs = (float*)(sm + W_CS);
    uint32_t sbase = smem_u32(sm);

    for (int e = tid; e < 512; e += 128) {
        int i = e >> 3, d4 = (e & 7) << 2;
        float4 qv = *(const float4*)(g_q + qbase + i * 256 + d4);
        float4 kv = *(const float4*)(g_k + qbase + i * 256 + d4);
        float4 vv = *(const float4*)(g_v + qbase + i * 256 + d4);
        uint2 hv, lv;
        uint32_t so = (uint32_t)(i * GP + d4) * 2;
        split4(qv, hv, lv);
        *(uint2*)(sm + AQ_HI + so) = hv; *(uint2*)(sm + AQ_LO + so) = lv;
        split4(kv, hv, lv);
        *(uint2*)(sm + AK_HI + so) = hv; *(uint2*)(sm + AK_LO + so) = lv;
        split4(vv, hv, lv);
        *(uint2*)(sm + AV_HI + so) = hv; *(uint2*)(sm + AV_LO + so) = lv;
    }
    if (tid == 0) {
        float run = 0.f;
        const float* dap = g_da + blk * 64;
        for (int j = 0; j < 64; j++) { run += dap[j]; cs[j] = run; }
    }
    __syncthreads();

    float sacc[8][4];
#pragma unroll
    for (int nj = 0; nj < 8; nj++)
#pragma unroll
        for (int e = 0; e < 4; e++) sacc[nj][e] = 0.f;
    s_reg(sbase, lane, w, sacc);
    mask_softmax_reg(lane, w, cs, sacc);

    // pack P fragments + export to gmem in fragment order
    uint32_t ph[8][2], pl[8][2];
    size_t pbase = (size_t)blk * 2048 + w * 512 + lane;
#pragma unroll
    for (int nj = 0; nj < 8; nj++) {
        ph[nj][0] = packsplit(sacc[nj][0], sacc[nj][1], pl[nj][0]);
        ph[nj][1] = packsplit(sacc[nj][2], sacc[nj][3], pl[nj][1]);
        g_qkwh[pbase + (nj * 2 + 0) * 32] = ph[nj][0];
        g_qkwh[pbase + (nj * 2 + 1) * 32] = ph[nj][1];
        g_qkwl[pbase + (nj * 2 + 0) * 32] = pl[nj][0];
        g_qkwl[pbase + (nj * 2 + 1) * 32] = pl[nj][1];
    }

    float facc[4][4];
#pragma unroll
    for (int nj = 0; nj < 4; nj++)
#pragma unroll
        for (int e = 0; e < 4; e++) facc[nj][e] = 0.f;
    pv_reg(sbase + AV_HI, sbase + AV_LO, lane, ph, pl, facc);

    float* vwp = g_vw + (size_t)blk * 2048;
    int gr = lane >> 2, gc2 = (lane & 3) << 1;
    int r0 = w * 16 + gr;
#pragma unroll
    for (int nj = 0; nj < 4; nj++) {
        int d0 = nj * 8 + gc2;
        float2 o0 = {facc[nj][0], facc[nj][1]};
        float2 o1 = {facc[nj][2], facc[nj][3]};
        *(float2*)(vwp + r0 * 32 + d0) = o0;
        *(float2*)(vwp + (r0 + 8) * 32 + d0) = o1;
    }
}

__global__ __launch_bounds__(128) void attn_h_kernel(void)
{
    extern __shared__ char sm[];
    int blk = blockIdx.x;
    int n = blk & 7;
    int x = (blk >> 3) & 63;
    int b = blk >> 9;
    int tid = threadIdx.x, lane = tid & 31, w = tid >> 5;
    int qbase = (b * 64 * 64 + x) * 256 + n * 32;
    float* cs = (float*)(sm + H_CS);
    uint32_t sbase = smem_u32(sm);

    for (int e = tid; e < 512; e += 128) {
        int i = e >> 3, d4 = (e & 7) << 2;
        float4 qv = *(const float4*)(g_q + qbase + i * 16384 + d4);
        float4 kv = *(const float4*)(g_k + qbase + i * 16384 + d4);
        float4 vv = *(const float4*)(g_v + qbase + i * 16384 + d4);
        float4 wv = *(const float4*)(g_vw + ((size_t)((b * 64 + i) * 8 + n)) * 2048 + x * 32 + d4);
        uint2 hv, lv;
        uint32_t so = (uint32_t)(i * GP + d4) * 2;
        split4(qv, hv, lv);
        *(uint2*)(sm + AQ_HI + so) = hv; *(uint2*)(sm + AQ_LO + so) = lv;
        split4(kv, hv, lv);
        *(uint2*)(sm + AK_HI + so) = hv; *(uint2*)(sm + AK_LO + so) = lv;
        split4(vv, hv, lv);
        *(uint2*)(sm + AV_HI + so) = hv; *(uint2*)(sm + AV_LO + so) = lv;
        split4(wv, hv, lv);
        *(uint2*)(sm + AW_HI + so) = hv; *(uint2*)(sm + AW_LO + so) = lv;
    }
    if (tid == 0) {
        float run = 0.f;
        const float* dbp = g_db + blk * 64;
        for (int j = 0; j < 64; j++) { run += dbp[j]; cs[j] = run; }
    }
    __syncthreads();

    float sacc[8][4];
#pragma unroll
    for (int nj = 0; nj < 8; nj++)
#pragma unroll
        for (int e = 0; e < 4; e++) sacc[nj][e] = 0.f;
    s_reg(sbase, lane, w, sacc);
    mask_softmax_reg(lane, w, cs, sacc);

    uint32_t ph[8][2], pl[8][2];
#pragma unroll
    for (int nj = 0; nj < 8; nj++) {
        ph[nj][0] = packsplit(sacc[nj][0], sacc[nj][1], pl[nj][0]);
        ph[nj][1] = packsplit(sacc[nj][2], sacc[nj][3], pl[nj][1]);
    }

    float facc1[4][4], facc2[4][4];
#pragma unroll
    for (int nj = 0; nj < 4; nj++)
#pragma unroll
        for (int e = 0; e < 4; e++) { facc1[nj][e] = 0.f; facc2[nj][e] = 0.f; }
    pv_reg(sbase + AV_HI, sbase + AV_LO, lane, ph, pl, facc1);
    pv_reg(sbase + AW_HI, sbase + AW_LO, lane, ph, pl, facc2);

    float* v2p = g_vh2 + (size_t)blk * 2048;
    int gr = lane >> 2, gc2 = (lane & 3) << 1;
    int r0 = w * 16 + gr;
#pragma unroll
    for (int nj = 0; nj < 4; nj++) {
        int d0 = nj * 8 + gc2;
        float2 o0 = {facc1[nj][0], facc1[nj][1]};
        float2 o1 = {facc1[nj][2], facc1[nj][3]};
        *(float2*)(v2p + r0 * 32 + d0) = o0;
        *(float2*)(v2p + (r0 + 8) * 32 + d0) = o1;
        float2 p0 = {0.5f * facc2[nj][0], 0.5f * facc2[nj][1]};
        float2 p1 = {0.5f * facc2[nj][2], 0.5f * facc2[nj][3]};
        *(float2*)(g_pre + (size_t)((b * 64 + r0) * 64 + x) * 256 + n * 32 + d0) = p0;
        *(float2*)(g_pre + (size_t)((b * 64 + r0 + 8) * 64 + x) * 256 + n * 32 + d0) = p1;
    }
}

// out2: final = pre + 0.5*(qk_w @ v_h2) + lepe -> bf16 hi/lo split
#define O2_VHI 0
#define O2_VLO 5120
#define OUT2_SMEM 10240

__global__ __launch_bounds__(128) void out2_kernel(void)
{
    extern __shared__ char sm[];
    int blk = blockIdx.x;
    int n = blk & 7;
    int y = (blk >> 3) & 63;
    int b = blk >> 9;
    int tid = threadIdx.x, lane = tid & 31, w = tid >> 5;
    uint32_t sbase = smem_u32(sm);

    // load P fragments (coalesced, fragment order)
    uint32_t ph[8][2], pl[8][2];
    size_t pbase = (size_t)blk * 2048 + w * 512 + lane;
#pragma unroll
    for (int nj = 0; nj < 8; nj++) {
        ph[nj][0] = g_qkwh[pbase + (nj * 2 + 0) * 32];
        ph[nj][1] = g_qkwh[pbase + (nj * 2 + 1) * 32];
        pl[nj][0] = g_qkwl[pbase + (nj * 2 + 0) * 32];
        pl[nj][1] = g_qkwl[pbase + (nj * 2 + 1) * 32];
    }

    for (int e = tid; e < 512; e += 128) {
        int j = e >> 3, d4 = (e & 7) << 2;
        float4 vv = *(const float4*)(g_vh2 + ((size_t)((b * 64 + j) * 8 + n)) * 2048 + y * 32 + d4);
        uint2 hv, lv;
        split4(vv, hv, lv);
        uint32_t so = (uint32_t)(j * GP + d4) * 2;
        *(uint2*)(sm + O2_VHI + so) = hv;
        *(uint2*)(sm + O2_VLO + so) = lv;
    }
    __syncthreads();

    float facc[4][4];
#pragma unroll
    for (int nj = 0; nj < 4; nj++)
#pragma unroll
        for (int e = 0; e < 4; e++) facc[nj][e] = 0.f;
    pv_reg(sbase + O2_VHI, sbase + O2_VLO, lane, ph, pl, facc);

    int gr = lane >> 2, gc2 = (lane & 3) << 1;
    int r0 = w * 16 + gr;
#pragma unroll
    for (int nj = 0; nj < 4; nj++) {
        int d0 = n * 32 + nj * 8 + gc2;
        size_t a0 = (size_t)((b * 64 + y) * 64 + r0) * 256 + d0;
        size_t a1 = (size_t)((b * 64 + y) * 64 + r0 + 8) * 256 + d0;
        float2 pr0 = *(float2*)(g_pre + a0);
        float2 le0 = *(float2*)(g_lepe + a0);
        float2 pr1 = *(float2*)(g_pre + a1);
        float2 le1 = *(float2*)(g_lepe + a1);
        float fx0 = pr0.x + 0.5f * facc[nj][0] + le0.x;
        float fy0 = pr0.y + 0.5f * facc[nj][1] + le0.y;
        float fx1 = pr1.x + 0.5f * facc[nj][2] + le1.x;
        float fy1 = pr1.y + 0.5f * facc[nj][3] + le1.y;
        uint32_t lo0, lo1;
        uint32_t hi0 = packsplit(fx0, fy0, lo0);
        uint32_t hi1 = packsplit(fx1, fy1, lo1);
        *(uint32_t*)(g_ahi + a0) = hi0;
        *(uint32_t*)(g_alo + a0) = lo0;
        *(uint32_t*)(g_ahi + a1) = hi1;
        *(uint32_t*)(g_alo + a1) = lo1;
    }
}

// ---------------- launch ----------------
extern "C" void kernel_launch(void* const* d_in, const int* in_sizes, int n_in,
                              void* d_out, int out_size)
{
    const float* x    = (const float*)d_in[0];
    const float* sinp = (const float*)d_in[1];
    const float* cosp = (const float*)d_in[2];
    const float* Wq   = (const float*)d_in[3];
    const float* bq   = (const float*)d_in[4];
    const float* Wk   = (const float*)d_in[5];
    const float* bk   = (const float*)d_in[6];
    const float* Wv   = (const float*)d_in[7];
    const float* bv   = (const float*)d_in[8];
    const float* Wo   = (const float*)d_in[9];
    const float* bo   = (const float*)d_in[10];
    const float* lw   = (const float*)d_in[11];
    const float* lb   = (const float*)d_in[12];
    const float* dtw  = (const float*)d_in[13];
    const float* dtb  = (const float*)d_in[14];
    const float* Alog = (const float*)d_in[15];
    float* out = (float*)d_out;

    const float scaling = 0.17677669529663687f;   // 32^-0.5

    cudaFuncSetAttribute(gemm_mma_kernel,
                         cudaFuncAttributeMaxDynamicSharedMemorySize, GEMM_SMEM);

    convW_kernel<<<dim3(64, 4), 256>>>(Wq, Wk, Wv, Wo);               // 0
    dtconv_kernel<<<NROW / 4, 256>>>(x, dtw, dtb, Alog);              // 1

    gemm_mma_kernel<<<dim3(6, 512), 256, GEMM_SMEM>>>(
        bq, bk, bv, nullptr, 0, scaling, sinp, cosp);                 // 2 (fused q/k/v)

    attn_w_kernel<<<Bn * Hn * Nn, 128, ATTN_SMEM_W>>>();              // 3 <- profiled
    attn_h_kernel<<<Bn * Wn * Nn, 128, ATTN_SMEM_H>>>();              // 4

    lepe_kernel<<<Bn * Hn * 2, 256>>>(lw, lb);                        // 5

    out2_kernel<<<Bn * Hn * Nn, 128, OUT2_SMEM>>>();                  // 6

    gemm_mma_kernel<<<dim3(2, 512), 256, GEMM_SMEM>>>(
        bo, nullptr, nullptr, out, 1, 1.0f, sinp, cosp);              // 7 (output proj)
}